// round 13
// baseline (speedup 1.0000x reference)
#include <cuda_runtime.h>
#include <cuda_fp16.h>
#include <cstdint>
#include <cstddef>

using f16 = __half;

// ================= device scratch (no allocations allowed) =================
__device__ __align__(16) f16 g_xh [8192 * 1024];
__device__ __align__(16) f16 g_xl [8192 * 1024];
__device__ __align__(16) f16 g_x1h[8192 * 256];
__device__ __align__(16) f16 g_x1l[8192 * 256];
__device__ __align__(16) f16 g_x2h[8192 * 128];
__device__ __align__(16) f16 g_x2l[8192 * 128];
__device__ __align__(16) f16 g_x3h[8192 * 64];
__device__ __align__(16) f16 g_x3l[8192 * 64];
__device__ __align__(16) f16 g_B1h[512 * 1024];
__device__ __align__(16) f16 g_B2h[256 * 256];
__device__ __align__(16) f16 g_B3h[128 * 128];
__device__ __align__(16) f16 g_B4h[1024 * 64];
__device__ float g_t1[8192 * 256];
__device__ float g_t2[8192 * 128];
__device__ float g_t3[8192 * 64];
__device__ float g_invn[3][8192];
__device__ float g_sb[3][8192];
__device__ float g_cb[3][8192];
__device__ float g_part1[256 * 256];
__device__ float g_part2[256 * 128];
__device__ float g_part3[256 * 64];
__device__ float g_rsH[512];          // slots: 0 / 256 / 384

// ================= helpers =================
__device__ __forceinline__ uint32_t smem_u32(const void* p) {
    uint32_t a;
    asm("{ .reg .u64 t; cvta.to.shared.u64 t, %1; cvt.u32.u64 %0, t; }"
        : "=r"(a) : "l"(p));
    return a;
}
__device__ __forceinline__ void ldsm4(uint32_t* r, uint32_t addr) {
    asm volatile("ldmatrix.sync.aligned.m8n8.x4.shared.b16 {%0,%1,%2,%3}, [%4];"
                 : "=r"(r[0]), "=r"(r[1]), "=r"(r[2]), "=r"(r[3]) : "r"(addr));
}
__device__ __forceinline__ void mma16816(float* d, const uint32_t* a, const uint32_t* b) {
    asm volatile(
        "mma.sync.aligned.m16n8k16.row.col.f32.f16.f16.f32 "
        "{%0,%1,%2,%3}, {%4,%5,%6,%7}, {%8,%9}, {%0,%1,%2,%3};"
        : "+f"(d[0]), "+f"(d[1]), "+f"(d[2]), "+f"(d[3])
        : "r"(a[0]), "r"(a[1]), "r"(a[2]), "r"(a[3]), "r"(b[0]), "r"(b[1]));
}
__device__ __forceinline__ void cp16(uint32_t dst, const void* src) {
    asm volatile("cp.async.cg.shared.global [%0], [%1], 16;"
                 :: "r"(dst), "l"(src) : "memory");
}
__device__ __forceinline__ void split1(float v, f16& h, f16& l) {
    h = __float2half_rn(v);
    l = __float2half_rn(v - __half2float(h));
}
__device__ __forceinline__ float warp_sum(float v) {
#pragma unroll
    for (int o = 16; o; o >>= 1) v += __shfl_down_sync(0xffffffffu, v, o);
    return v;
}

// ================= fp16 GEMM: 2-pass for W columns, 1-pass for T columns ====
// D[m,n] = (Ah+Al)[m,:] . Bh[n,:] (n < NW)  |  Ah[m,:] . Bh[n,:] (n >= NW)
// 3-stage cp.async pipeline.
#define LDH2    40                      // halfwords per row (32 + 8 pad)
#define TILE_B2 (128 * LDH2 * 2)        // 10240
#define STG     (3 * TILE_B2)           // 30720 (Ah, Al, Bh)
#define GEMM_SMEM (3 * STG)             // 92160

__global__ __launch_bounds__(256, 2)
void gemm_mma(const f16* __restrict__ Ah, const f16* __restrict__ Al,
              const f16* __restrict__ Bh,
              const float* __restrict__ bias, const float* __restrict__ mask,
              f16* __restrict__ Xh, f16* __restrict__ Xl,
              float* __restrict__ Xf, float* __restrict__ Tout,
              int K, int NW, int NT) {
    extern __shared__ char smem[];
    const uint32_t sbase = smem_u32(smem);
    const int tid = threadIdx.x;
    const int lane = tid & 31;
    const int warp = tid >> 5;
    const int wm = warp >> 1;
    const int wn = warp & 1;
    const int bm = blockIdx.y * 128;
    const int bn = blockIdx.x * 128;
    const int NC = K >> 5;
    // warp-uniform: this warp's 64-col span is W (2-pass) or T (1-pass).
    // NW is a multiple of 64 whenever NT > 0, so the span never straddles.
    const bool twoPass = (bn + wn * 64) < NW;

    const int row8 = tid >> 2;          // 0..63
    const int q8 = (tid & 3) * 8;

    float acc[2][8][4];
#pragma unroll
    for (int i = 0; i < 2; i++)
#pragma unroll
        for (int j = 0; j < 8; j++)
#pragma unroll
            for (int q = 0; q < 4; q++) acc[i][j][q] = 0.f;

    auto issue = [&](int c, int buf) {
        int k0 = c << 5;
        uint32_t st = sbase + buf * STG;
#pragma unroll
        for (int i = 0; i < 2; i++) {
            int r = row8 + 64 * i;
            uint32_t off = (uint32_t)(r * LDH2 + q8) * 2;
            const size_t ao = (size_t)(bm + r) * K + k0 + q8;
            const size_t bo = (size_t)(bn + r) * K + k0 + q8;
            cp16(st + off, Ah + ao);
            cp16(st + TILE_B2 + off, Al + ao);
            cp16(st + 2 * TILE_B2 + off, Bh + bo);
        }
    };

    // prologue: fill up to 3 stages
#pragma unroll
    for (int s = 0; s < 3; s++) {
        if (s < NC) issue(s, s);
        asm volatile("cp.async.commit_group;" ::: "memory");
    }

    const int rl = lane & 15, ka = (lane >> 4) * 8;
    const int sec = lane >> 3;
    const int nloc = ((sec & 2) ? 8 : 0) + (lane & 7);
    const int kb = (sec & 1) * 8;

    for (int c = 0; c < NC; c++) {
        asm volatile("cp.async.wait_group 2;" ::: "memory");
        __syncthreads();
        const uint32_t stb = sbase + (uint32_t)(c % 3) * STG;
        if (twoPass) {
#pragma unroll
            for (int kk = 0; kk < 32; kk += 16) {
                uint32_t ah[2][4], al[2][4];
#pragma unroll
                for (int i = 0; i < 2; i++) {
                    uint32_t off = (uint32_t)((wm * 32 + i * 16 + rl) * LDH2 + kk + ka) * 2;
                    ldsm4(ah[i], stb + off);
                    ldsm4(al[i], stb + TILE_B2 + off);
                }
                uint32_t b[8][2];
#pragma unroll
                for (int p = 0; p < 4; p++) {
                    uint32_t r4[4];
                    ldsm4(r4, stb + 2 * TILE_B2 +
                              (uint32_t)((wn * 64 + p * 16 + nloc) * LDH2 + kk + kb) * 2);
                    b[2 * p][0] = r4[0]; b[2 * p][1] = r4[1];
                    b[2 * p + 1][0] = r4[2]; b[2 * p + 1][1] = r4[3];
                }
#pragma unroll
                for (int i = 0; i < 2; i++)
#pragma unroll
                    for (int j = 0; j < 8; j++) {
                        mma16816(acc[i][j], ah[i], b[j]);
                        mma16816(acc[i][j], al[i], b[j]);
                    }
            }
        } else {
#pragma unroll
            for (int kk = 0; kk < 32; kk += 16) {
                uint32_t ah[2][4];
#pragma unroll
                for (int i = 0; i < 2; i++) {
                    uint32_t off = (uint32_t)((wm * 32 + i * 16 + rl) * LDH2 + kk + ka) * 2;
                    ldsm4(ah[i], stb + off);
                }
                uint32_t b[8][2];
#pragma unroll
                for (int p = 0; p < 4; p++) {
                    uint32_t r4[4];
                    ldsm4(r4, stb + 2 * TILE_B2 +
                              (uint32_t)((wn * 64 + p * 16 + nloc) * LDH2 + kk + kb) * 2);
                    b[2 * p][0] = r4[0]; b[2 * p][1] = r4[1];
                    b[2 * p + 1][0] = r4[2]; b[2 * p + 1][1] = r4[3];
                }
#pragma unroll
                for (int i = 0; i < 2; i++)
#pragma unroll
                    for (int j = 0; j < 8; j++)
                        mma16816(acc[i][j], ah[i], b[j]);
            }
        }
        __syncthreads();
        if (c + 3 < NC) issue(c + 3, (c + 3) % 3);
        asm volatile("cp.async.commit_group;" ::: "memory");
    }

    // ---- epilogue ----
    const int rq = lane >> 2;
    const int cq = (lane & 3) * 2;
    const int Ntot = NW + NT;
#pragma unroll
    for (int i = 0; i < 2; i++) {
        int r0 = bm + wm * 32 + i * 16 + rq;
        int r1 = r0 + 8;
#pragma unroll
        for (int j = 0; j < 8; j++) {
            int c0 = bn + wn * 64 + j * 8 + cq;
            float v00 = acc[i][j][0], v01 = acc[i][j][1];
            float v10 = acc[i][j][2], v11 = acc[i][j][3];
            if (c0 < NW) {
                float bb0 = bias[c0], bb1 = bias[c0 + 1];
                v00 = fmaxf(v00 + bb0, 0.f); v01 = fmaxf(v01 + bb1, 0.f);
                v10 = fmaxf(v10 + bb0, 0.f); v11 = fmaxf(v11 + bb1, 0.f);
                if (mask) {
                    float m0 = mask[c0], m1 = mask[c0 + 1];
                    v00 *= m0; v01 *= m1; v10 *= m0; v11 *= m1;
                }
                if (Xh) {
                    f16 h, l;
                    __half2 hp, lp;
                    split1(v00, h, l); hp.x = h; lp.x = l;
                    split1(v01, h, l); hp.y = h; lp.y = l;
                    *reinterpret_cast<__half2*>(Xh + (size_t)r0 * NW + c0) = hp;
                    *reinterpret_cast<__half2*>(Xl + (size_t)r0 * NW + c0) = lp;
                    split1(v10, h, l); hp.x = h; lp.x = l;
                    split1(v11, h, l); hp.y = h; lp.y = l;
                    *reinterpret_cast<__half2*>(Xh + (size_t)r1 * NW + c0) = hp;
                    *reinterpret_cast<__half2*>(Xl + (size_t)r1 * NW + c0) = lp;
                } else {
                    *reinterpret_cast<float2*>(Xf + (size_t)r0 * NW + c0) =
                        make_float2(v00, v01);
                    *reinterpret_cast<float2*>(Xf + (size_t)r1 * NW + c0) =
                        make_float2(v10, v11);
                }
            } else if (c0 < Ntot) {
                int tc = c0 - NW;
                *reinterpret_cast<float2*>(Tout + (size_t)r0 * NT + tc) =
                    make_float2(v00, v01);
                *reinterpret_cast<float2*>(Tout + (size_t)r1 * NT + tc) =
                    make_float2(v10, v11);
            }
        }
    }
}

// ================= conversion kernels =================
// weights: fp32 -> fp16 round. 7 segments.
__global__ void split_weights(const float* W1, const float* H1, const float* W2,
                              const float* H2, const float* W3, const float* H3,
                              const float* W4,
                              f16* B1h, f16* B2h, f16* B3h, f16* B4h) {
    const float* src; f16* dh; int n, ntot;
    switch (blockIdx.y) {
        case 0: src = W1; dh = B1h;            n = 256*1024; ntot = n; break;
        case 1: src = H1; dh = B1h + 256*1024; n = 256*1024; ntot = n; break;
        case 2: src = W2; dh = B2h;            n = 128*256;  ntot = n; break;
        case 3: src = H2; dh = B2h + 128*256;  n = 128*256;  ntot = n; break;
        case 4: src = W3; dh = B3h;            n = 64*128;   ntot = n; break;
        case 5: src = H3; dh = B3h + 64*128;   n = 64*128;   ntot = n; break;
        default: src = W4; dh = B4h;           n = 1000*64;  ntot = 1024*64; break;
    }
    for (int i = (blockIdx.x * blockDim.x + threadIdx.x) * 4; i < ntot;
         i += gridDim.x * blockDim.x * 4) {
        float4 v;
        if (i + 3 < n) v = *reinterpret_cast<const float4*>(src + i);
        else v = make_float4(i < n ? src[i] : 0.f, i + 1 < n ? src[i + 1] : 0.f,
                             i + 2 < n ? src[i + 2] : 0.f, i + 3 < n ? src[i + 3] : 0.f);
        __half2 hp0, hp1;
        hp0.x = __float2half_rn(v.x); hp0.y = __float2half_rn(v.y);
        hp1.x = __float2half_rn(v.z); hp1.y = __float2half_rn(v.w);
        reinterpret_cast<__half2*>(dh + i)[0] = hp0;
        reinterpret_cast<__half2*>(dh + i)[1] = hp1;
    }
}

__global__ void rowstats_split(const float* __restrict__ X, float* __restrict__ invn,
                               float* __restrict__ rs, f16* __restrict__ xh,
                               f16* __restrict__ xl) {
    int b = blockIdx.x, t = threadIdx.x;   // 256 threads
    const float* row = X + (size_t)b * 1024;
    float4 v = *reinterpret_cast<const float4*>(row + t * 4);
    f16 h, l;
    __half2 hp0, hp1, lp0, lp1;
    split1(v.x, h, l); hp0.x = h; lp0.x = l;
    split1(v.y, h, l); hp0.y = h; lp0.y = l;
    split1(v.z, h, l); hp1.x = h; lp1.x = l;
    split1(v.w, h, l); hp1.y = h; lp1.y = l;
    size_t o = (size_t)b * 1024 + t * 4;
    reinterpret_cast<__half2*>(xh + o)[0] = hp0;
    reinterpret_cast<__half2*>(xh + o)[1] = hp1;
    reinterpret_cast<__half2*>(xl + o)[0] = lp0;
    reinterpret_cast<__half2*>(xl + o)[1] = lp1;
    float s = v.x + v.y + v.z + v.w;
    float ss = fmaf(v.x, v.x, fmaf(v.y, v.y, fmaf(v.z, v.z, v.w * v.w)));
    __shared__ float shs[8], shss[8];
    s = warp_sum(s); ss = warp_sum(ss);
    int w = t >> 5, lid = t & 31;
    if (lid == 0) { shs[w] = s; shss[w] = ss; }
    __syncthreads();
    if (t == 0) {
        float ts = 0.f, tss = 0.f;
#pragma unroll
        for (int i = 0; i < 8; i++) { ts += shs[i]; tss += shss[i]; }
        invn[b] = rsqrtf(tss);
        rs[b] = ts;
    }
}

__global__ void rowstats_hl(const f16* __restrict__ hi, const f16* __restrict__ lo,
                            int D, float* __restrict__ invn, float* __restrict__ rs) {
    int b = blockIdx.x, t = threadIdx.x;   // 128 threads
    float s = 0.f, ss = 0.f;
    for (int i = t; i < D; i += 128) {
        float v = __half2float(hi[(size_t)b * D + i]) +
                  __half2float(lo[(size_t)b * D + i]);
        s += v;
        ss = fmaf(v, v, ss);
    }
    __shared__ float shs[4], shss[4];
    s = warp_sum(s); ss = warp_sum(ss);
    int w = t >> 5, lid = t & 31;
    if (lid == 0) { shs[w] = s; shss[w] = ss; }
    __syncthreads();
    if (t == 0) {
        float ts = 0.f, tss = 0.f;
#pragma unroll
        for (int i = 0; i < 4; i++) { ts += shs[i]; tss += shss[i]; }
        invn[b] = rsqrtf(tss);
        rs[b] = ts;
    }
}

// ================= hebbian-path kernels =================
__global__ void cb_kernel(const float* __restrict__ T, int Y,
                          const float* __restrict__ invnx, const float* __restrict__ sb,
                          float* __restrict__ cb) {
    int wrp = (blockIdx.x * blockDim.x + threadIdx.x) >> 5;
    int lane = threadIdx.x & 31;
    if (wrp >= 8192) return;
    const float* row = T + (size_t)wrp * Y;
    float ss = 0.f;
    for (int i = lane; i < Y; i += 32) { float v = row[i]; ss = fmaf(v, v, ss); }
    ss = warp_sum(ss);
    if (lane == 0) cb[wrp] = sb[wrp] * invnx[wrp] * rsqrtf(ss);
}

__global__ void hebb_kernel(const float* __restrict__ T, int Y,
                            const float* __restrict__ cb, float* __restrict__ part) {
    int j = threadIdx.x;
    int b0 = blockIdx.x * 32;
    float a0 = 0.f, a1 = 0.f, a2 = 0.f, a3 = 0.f;
#pragma unroll
    for (int b = b0; b < b0 + 32; b += 4) {
        a0 = fmaf(T[(size_t)b * Y + j],       cb[b],     a0);
        a1 = fmaf(T[(size_t)(b + 1) * Y + j], cb[b + 1], a1);
        a2 = fmaf(T[(size_t)(b + 2) * Y + j], cb[b + 2], a2);
        a3 = fmaf(T[(size_t)(b + 3) * Y + j], cb[b + 3], a3);
    }
    part[blockIdx.x * Y + j] = (a0 + a1) + (a2 + a3);
}

__global__ void rowsum_kernel(const float* __restrict__ H, int D,
                              float* __restrict__ out) {
    int row = blockIdx.x, t = threadIdx.x;   // 128 threads
    float s = 0.f;
    for (int i = t; i < D; i += 128) s += H[(size_t)row * D + i];
    __shared__ float sh[4];
    s = warp_sum(s);
    if ((t & 31) == 0) sh[t >> 5] = s;
    __syncthreads();
    if (t == 0) out[row] = sh[0] + sh[1] + sh[2] + sh[3];
}

__global__ void score_kernel(const float* __restrict__ rsH, const float* __restrict__ part,
                             int Y, float* __restrict__ hm) {
    int j = threadIdx.x;
    float hb = 0.f;
    for (int p = 0; p < 256; p++) hb += part[p * Y + j];
    float theta = 1.0f / (float)Y;
    float sc = fmaf(1.0f - theta, rsH[j], hb);
    __shared__ float smin[256], smax[256];
    smin[j] = sc; smax[j] = sc;
    __syncthreads();
    for (int s = blockDim.x >> 1; s > 0; s >>= 1) {
        if (j < s) {
            smin[j] = fminf(smin[j], smin[j + s]);
            smax[j] = fmaxf(smax[j], smax[j + s]);
        }
        __syncthreads();
    }
    float mn = smin[0], mx = smax[0];
    float norm = (sc - mn) / (mx - mn + 1e-8f);
    hm[j] = (norm < 0.5f) ? 0.0f : 1.0f;
}

// ================= launcher (exact R9/R12 schedule) =================
extern "C" void kernel_launch(void* const* d_in, const int* in_sizes, int n_in,
                              void* d_out, int out_size) {
    const float* x     = (const float*)d_in[0];
    const float* mask0 = (const float*)d_in[1];
    const float* mask1 = (const float*)d_in[2];
    const float* mask2 = (const float*)d_in[3];
    const float* W1 = (const float*)d_in[4];
    const float* b1 = (const float*)d_in[5];
    const float* W2 = (const float*)d_in[6];
    const float* b2 = (const float*)d_in[7];
    const float* W3 = (const float*)d_in[8];
    const float* b3 = (const float*)d_in[9];
    const float* W4 = (const float*)d_in[10];
    const float* b4 = (const float*)d_in[11];
    const float* H1 = (const float*)d_in[12];
    const float* H2 = (const float*)d_in[13];
    const float* H3 = (const float*)d_in[14];
    float* out = (float*)d_out;

    f16 *xh, *xl, *x1h, *x1l, *x2h, *x2l, *x3h, *x3l;
    f16 *B1h, *B2h, *B3h, *B4h;
    float *t1, *t2, *t3, *invn, *sbp, *cbp, *part1, *part2, *part3, *rsH;
    cudaGetSymbolAddress((void**)&xh, g_xh);   cudaGetSymbolAddress((void**)&xl, g_xl);
    cudaGetSymbolAddress((void**)&x1h, g_x1h); cudaGetSymbolAddress((void**)&x1l, g_x1l);
    cudaGetSymbolAddress((void**)&x2h, g_x2h); cudaGetSymbolAddress((void**)&x2l, g_x2l);
    cudaGetSymbolAddress((void**)&x3h, g_x3h); cudaGetSymbolAddress((void**)&x3l, g_x3l);
    cudaGetSymbolAddress((void**)&B1h, g_B1h);
    cudaGetSymbolAddress((void**)&B2h, g_B2h);
    cudaGetSymbolAddress((void**)&B3h, g_B3h);
    cudaGetSymbolAddress((void**)&B4h, g_B4h);
    cudaGetSymbolAddress((void**)&t1, g_t1);
    cudaGetSymbolAddress((void**)&t2, g_t2);
    cudaGetSymbolAddress((void**)&t3, g_t3);
    cudaGetSymbolAddress((void**)&invn, g_invn);
    cudaGetSymbolAddress((void**)&sbp, g_sb);
    cudaGetSymbolAddress((void**)&cbp, g_cb);
    cudaGetSymbolAddress((void**)&part1, g_part1);
    cudaGetSymbolAddress((void**)&part2, g_part2);
    cudaGetSymbolAddress((void**)&part3, g_part3);
    cudaGetSymbolAddress((void**)&rsH, g_rsH);

    float* invn1 = invn;        float* invn2 = invn + 8192;  float* invn3 = invn + 16384;
    float* sb1 = sbp;           float* sb2 = sbp + 8192;     float* sb3 = sbp + 16384;
    float* cb1 = cbp;           float* cb2 = cbp + 8192;     float* cb3 = cbp + 16384;

    static bool inited = false;
    static cudaStream_t s1, s2, s3;
    static cudaEvent_t eFork, eW, eR, eX, eG1, eG2, eG3, eS1, eS2, eS3;
    if (!inited) {
        cudaFuncSetAttribute(gemm_mma, cudaFuncAttributeMaxDynamicSharedMemorySize,
                             GEMM_SMEM);
        int leastPri, greatestPri;
        cudaDeviceGetStreamPriorityRange(&leastPri, &greatestPri);
        cudaStreamCreateWithPriority(&s1, cudaStreamNonBlocking, leastPri);
        cudaStreamCreateWithPriority(&s2, cudaStreamNonBlocking, leastPri);
        cudaStreamCreateWithPriority(&s3, cudaStreamNonBlocking, leastPri);
        cudaEventCreateWithFlags(&eFork, cudaEventDisableTiming);
        cudaEventCreateWithFlags(&eW, cudaEventDisableTiming);
        cudaEventCreateWithFlags(&eR, cudaEventDisableTiming);
        cudaEventCreateWithFlags(&eX, cudaEventDisableTiming);
        cudaEventCreateWithFlags(&eG1, cudaEventDisableTiming);
        cudaEventCreateWithFlags(&eG2, cudaEventDisableTiming);
        cudaEventCreateWithFlags(&eG3, cudaEventDisableTiming);
        cudaEventCreateWithFlags(&eS1, cudaEventDisableTiming);
        cudaEventCreateWithFlags(&eS2, cudaEventDisableTiming);
        cudaEventCreateWithFlags(&eS3, cudaEventDisableTiming);
        inited = true;
    }

    const int B = 8192;
    const size_t OUT_OFF = (size_t)B * 1000;

    // ---- fork side streams off the capture stream ----
    cudaEventRecord(eFork, 0);
    cudaStreamWaitEvent(s1, eFork, 0);
    cudaStreamWaitEvent(s2, eFork, 0);
    cudaStreamWaitEvent(s3, eFork, 0);

    // s1: weight conversion (gates gemm1)
    split_weights<<<dim3(256, 7), 256, 0, s1>>>(W1, H1, W2, H2, W3, H3, W4,
                                                B1h, B2h, B3h, B4h);
    cudaEventRecord(eW, s1);

    // s2: H rowsums (score gates)
    rowsum_kernel<<<256, 128, 0, s2>>>(H1, 1024, rsH);
    rowsum_kernel<<<128, 128, 0, s2>>>(H2, 256, rsH + 256);
    rowsum_kernel<<<64, 128, 0, s2>>>(H3, 128, rsH + 384);
    cudaEventRecord(eR, s2);

    // s0: x conversion + stats
    rowstats_split<<<B, 256>>>(x, invn1, sb1, xh, xl);
    cudaEventRecord(eX, 0);

    // ======== critical GEMM chain on s0 (combined W+H tiles) ========
    cudaStreamWaitEvent(0, eW, 0);
    gemm_mma<<<dim3(4, 64), 256, GEMM_SMEM>>>(xh, xl, B1h, b1, mask0,
                                              x1h, x1l, nullptr, t1, 1024, 256, 256);
    cudaEventRecord(eG1, 0);
    gemm_mma<<<dim3(2, 64), 256, GEMM_SMEM>>>(x1h, x1l, B2h, b2, mask1,
                                              x2h, x2l, nullptr, t2, 256, 128, 128);
    cudaEventRecord(eG2, 0);
    gemm_mma<<<dim3(1, 64), 256, GEMM_SMEM>>>(x2h, x2l, B3h, b3, mask2,
                                              x3h, x3l, nullptr, t3, 128, 64, 64);
    cudaEventRecord(eG3, 0);
    gemm_mma<<<dim3(8, 64), 256, GEMM_SMEM>>>(x3h, x3l, B4h, b4,
                                              (const float*)nullptr,
                                              (f16*)nullptr, (f16*)nullptr,
                                              out, (float*)nullptr, 64, 1000, 0);

    // ======== layer-1 hebbian on s1 ========
    cudaStreamWaitEvent(s1, eG1, 0);
    cudaStreamWaitEvent(s1, eX, 0);
    cudaStreamWaitEvent(s1, eR, 0);
    cb_kernel<<<1024, 256, 0, s1>>>(t1, 256, invn1, sb1, cb1);
    hebb_kernel<<<256, 256, 0, s1>>>(t1, 256, cb1, part1);
    score_kernel<<<1, 256, 0, s1>>>(rsH, part1, 256, out + OUT_OFF);
    cudaEventRecord(eS1, s1);

    // ======== layer-2 hebbian on s2 ========
    cudaStreamWaitEvent(s2, eG1, 0);
    rowstats_hl<<<B, 128, 0, s2>>>(x1h, x1l, 256, invn2, sb2);
    cudaStreamWaitEvent(s2, eG2, 0);
    cb_kernel<<<1024, 256, 0, s2>>>(t2, 128, invn2, sb2, cb2);
    hebb_kernel<<<256, 128, 0, s2>>>(t2, 128, cb2, part2);
    score_kernel<<<1, 128, 0, s2>>>(rsH + 256, part2, 128, out + OUT_OFF + 256);
    cudaEventRecord(eS2, s2);

    // ======== layer-3 hebbian on s3 ========
    cudaStreamWaitEvent(s3, eG2, 0);
    rowstats_hl<<<B, 128, 0, s3>>>(x2h, x2l, 128, invn3, sb3);
    cudaStreamWaitEvent(s3, eG3, 0);
    cudaStreamWaitEvent(s3, eR, 0);
    cb_kernel<<<1024, 256, 0, s3>>>(t3, 64, invn3, sb3, cb3);
    hebb_kernel<<<256, 64, 0, s3>>>(t3, 64, cb3, part3);
    score_kernel<<<1, 64, 0, s3>>>(rsH + 384, part3, 64, out + OUT_OFF + 384);
    cudaEventRecord(eS3, s3);

    // ---- join ----
    cudaStreamWaitEvent(0, eS1, 0);
    cudaStreamWaitEvent(0, eS2, 0);
    cudaStreamWaitEvent(0, eS3, 0);
}

// round 14
// speedup vs baseline: 1.0591x; 1.0591x over previous
#include <cuda_runtime.h>
#include <cuda_fp16.h>
#include <cstdint>
#include <cstddef>

using f16 = __half;

// ================= device scratch (no allocations allowed) =================
__device__ __align__(16) f16 g_xh [8192 * 1024];
__device__ __align__(16) f16 g_xl [8192 * 1024];
__device__ __align__(16) f16 g_x1h[8192 * 256];
__device__ __align__(16) f16 g_x1l[8192 * 256];
__device__ __align__(16) f16 g_x2h[8192 * 128];
__device__ __align__(16) f16 g_x2l[8192 * 128];
__device__ __align__(16) f16 g_x3h[8192 * 64];
__device__ __align__(16) f16 g_x3l[8192 * 64];
__device__ __align__(16) f16 g_B1h[512 * 1024];
__device__ __align__(16) f16 g_B2h[256 * 256];
__device__ __align__(16) f16 g_B3h[128 * 128];
__device__ __align__(16) f16 g_B4h[1024 * 64];
__device__ float g_t1[8192 * 256];
__device__ float g_t2[8192 * 128];
__device__ float g_t3[8192 * 64];
__device__ float g_invn[3][8192];
__device__ float g_sb[3][8192];
__device__ float g_cb[3][8192];
__device__ float g_part1[256 * 256];
__device__ float g_part2[256 * 128];
__device__ float g_part3[256 * 64];
__device__ float g_rsH[512];          // slots: 0 / 256 / 384

// ================= helpers =================
__device__ __forceinline__ uint32_t smem_u32(const void* p) {
    uint32_t a;
    asm("{ .reg .u64 t; cvta.to.shared.u64 t, %1; cvt.u32.u64 %0, t; }"
        : "=r"(a) : "l"(p));
    return a;
}
__device__ __forceinline__ void ldsm4(uint32_t* r, uint32_t addr) {
    asm volatile("ldmatrix.sync.aligned.m8n8.x4.shared.b16 {%0,%1,%2,%3}, [%4];"
                 : "=r"(r[0]), "=r"(r[1]), "=r"(r[2]), "=r"(r[3]) : "r"(addr));
}
__device__ __forceinline__ void mma16816(float* d, const uint32_t* a, const uint32_t* b) {
    asm volatile(
        "mma.sync.aligned.m16n8k16.row.col.f32.f16.f16.f32 "
        "{%0,%1,%2,%3}, {%4,%5,%6,%7}, {%8,%9}, {%0,%1,%2,%3};"
        : "+f"(d[0]), "+f"(d[1]), "+f"(d[2]), "+f"(d[3])
        : "r"(a[0]), "r"(a[1]), "r"(a[2]), "r"(a[3]), "r"(b[0]), "r"(b[1]));
}
__device__ __forceinline__ void cp16(uint32_t dst, const void* src) {
    asm volatile("cp.async.cg.shared.global [%0], [%1], 16;"
                 :: "r"(dst), "l"(src) : "memory");
}
__device__ __forceinline__ void split1(float v, f16& h, f16& l) {
    h = __float2half_rn(v);
    l = __float2half_rn(v - __half2float(h));
}
__device__ __forceinline__ float warp_sum(float v) {
#pragma unroll
    for (int o = 16; o; o >>= 1) v += __shfl_down_sync(0xffffffffu, v, o);
    return v;
}

// ================= fp16 2-pass GEMM, templated tile shape ===================
// D[m,n] = (Ah+Al)[m,:] . Bh[n,:]  via  Ah·Bh + Al·Bh
// MB = m-tiles(16) per warp (BM = 64*MB); NB = n-tiles(16) per CTA (BN = 16*NB).
// 3-stage cp.async pipeline. 8 warps: wm in 0..3 (m), wn in 0..1 (n halves).
#define LDH2 40                          // halfwords per row (32 + 8 pad)

template <int MB, int NB>
__global__ __launch_bounds__(256, 2)
void gemm_mma(const f16* __restrict__ Ah, const f16* __restrict__ Al,
              const f16* __restrict__ Bh,
              const float* __restrict__ bias, const float* __restrict__ mask,
              f16* __restrict__ Xh, f16* __restrict__ Xl,
              float* __restrict__ Xf, float* __restrict__ Tout,
              int K, int NW, int NT) {
    constexpr int BM = 64 * MB;
    constexpr int BN = 16 * NB;
    constexpr int TILE_A = BM * LDH2 * 2;      // one A buffer (Ah or Al)
    constexpr int TILE_Bb = BN * LDH2 * 2;
    constexpr int STG = 2 * TILE_A + TILE_Bb;
    extern __shared__ char smem[];
    const uint32_t sbase = smem_u32(smem);
    const int tid = threadIdx.x;
    const int lane = tid & 31;
    const int warp = tid >> 5;
    const int wm = warp >> 1;                  // 0..3
    const int wn = warp & 1;                   // 0..1
    const int bm = blockIdx.y * BM;
    const int bn = blockIdx.x * BN;
    const int NC = K >> 5;

    const int row8 = tid >> 2;                 // 0..63
    const int q8 = (tid & 3) * 8;

    float acc[MB][NB][4];
#pragma unroll
    for (int i = 0; i < MB; i++)
#pragma unroll
        for (int j = 0; j < NB; j++)
#pragma unroll
            for (int q = 0; q < 4; q++) acc[i][j][q] = 0.f;

    auto issue = [&](int c, int buf) {
        int k0 = c << 5;
        uint32_t st = sbase + buf * STG;
#pragma unroll
        for (int i = 0; i < MB; i++) {         // A: BM rows, 64 per round
            int r = row8 + 64 * i;
            uint32_t off = (uint32_t)(r * LDH2 + q8) * 2;
            const size_t ao = (size_t)(bm + r) * K + k0 + q8;
            cp16(st + off, Ah + ao);
            cp16(st + TILE_A + off, Al + ao);
        }
#pragma unroll
        for (int i = 0; i < NB / 4; i++) {     // B: BN rows, 64 per round
            int r = row8 + 64 * i;
            uint32_t off = (uint32_t)(r * LDH2 + q8) * 2;
            const size_t bo = (size_t)(bn + r) * K + k0 + q8;
            cp16(st + 2 * TILE_A + off, Bh + bo);
        }
    };

    // prologue: fill up to 3 stages
#pragma unroll
    for (int s = 0; s < 3; s++) {
        if (s < NC) issue(s, s);
        asm volatile("cp.async.commit_group;" ::: "memory");
    }

    const int rl = lane & 15, ka = (lane >> 4) * 8;
    const int sec = lane >> 3;
    const int nloc = ((sec & 2) ? 8 : 0) + (lane & 7);
    const int kb = (sec & 1) * 8;

    for (int c = 0; c < NC; c++) {
        asm volatile("cp.async.wait_group 2;" ::: "memory");
        __syncthreads();
        const uint32_t stb = sbase + (uint32_t)(c % 3) * STG;
#pragma unroll
        for (int kk = 0; kk < 32; kk += 16) {
            uint32_t ah[MB][4], al[MB][4];
#pragma unroll
            for (int i = 0; i < MB; i++) {
                uint32_t off =
                    (uint32_t)((wm * (MB * 16) + i * 16 + rl) * LDH2 + kk + ka) * 2;
                ldsm4(ah[i], stb + off);
                ldsm4(al[i], stb + TILE_A + off);
            }
            uint32_t b[NB][2];
#pragma unroll
            for (int p = 0; p < NB / 2; p++) {
                uint32_t r4[4];
                ldsm4(r4, stb + 2 * TILE_A +
                          (uint32_t)((wn * (NB * 8) + p * 16 + nloc) * LDH2 + kk + kb) * 2);
                b[2 * p][0] = r4[0]; b[2 * p][1] = r4[1];
                b[2 * p + 1][0] = r4[2]; b[2 * p + 1][1] = r4[3];
            }
#pragma unroll
            for (int i = 0; i < MB; i++)
#pragma unroll
                for (int j = 0; j < NB; j++) {
                    mma16816(acc[i][j], ah[i], b[j]);
                    mma16816(acc[i][j], al[i], b[j]);
                }
        }
        __syncthreads();
        if (c + 3 < NC) issue(c + 3, (c + 3) % 3);
        asm volatile("cp.async.commit_group;" ::: "memory");
    }

    // ---- epilogue ----
    const int rq = lane >> 2;
    const int cq = (lane & 3) * 2;
    const int Ntot = NW + NT;
#pragma unroll
    for (int i = 0; i < MB; i++) {
        int r0 = bm + wm * (MB * 16) + i * 16 + rq;
        int r1 = r0 + 8;
#pragma unroll
        for (int j = 0; j < NB; j++) {
            int c0 = bn + wn * (NB * 8) + j * 8 + cq;
            float v00 = acc[i][j][0], v01 = acc[i][j][1];
            float v10 = acc[i][j][2], v11 = acc[i][j][3];
            if (c0 < NW) {
                float bb0 = bias[c0], bb1 = bias[c0 + 1];
                v00 = fmaxf(v00 + bb0, 0.f); v01 = fmaxf(v01 + bb1, 0.f);
                v10 = fmaxf(v10 + bb0, 0.f); v11 = fmaxf(v11 + bb1, 0.f);
                if (mask) {
                    float m0 = mask[c0], m1 = mask[c0 + 1];
                    v00 *= m0; v01 *= m1; v10 *= m0; v11 *= m1;
                }
                if (Xh) {
                    f16 h, l;
                    __half2 hp, lp;
                    split1(v00, h, l); hp.x = h; lp.x = l;
                    split1(v01, h, l); hp.y = h; lp.y = l;
                    *reinterpret_cast<__half2*>(Xh + (size_t)r0 * NW + c0) = hp;
                    *reinterpret_cast<__half2*>(Xl + (size_t)r0 * NW + c0) = lp;
                    split1(v10, h, l); hp.x = h; lp.x = l;
                    split1(v11, h, l); hp.y = h; lp.y = l;
                    *reinterpret_cast<__half2*>(Xh + (size_t)r1 * NW + c0) = hp;
                    *reinterpret_cast<__half2*>(Xl + (size_t)r1 * NW + c0) = lp;
                } else {
                    *reinterpret_cast<float2*>(Xf + (size_t)r0 * NW + c0) =
                        make_float2(v00, v01);
                    *reinterpret_cast<float2*>(Xf + (size_t)r1 * NW + c0) =
                        make_float2(v10, v11);
                }
            } else if (c0 < Ntot) {
                int tc = c0 - NW;
                *reinterpret_cast<float2*>(Tout + (size_t)r0 * NT + tc) =
                    make_float2(v00, v01);
                *reinterpret_cast<float2*>(Tout + (size_t)r1 * NT + tc) =
                    make_float2(v10, v11);
            }
        }
    }
}

// smem sizes per instantiation (3 stages)
#define SM_28 (3 * (2 * (128 * LDH2 * 2) + 128 * LDH2 * 2))   // 92160
#define SM_18 (3 * (2 * (64 * LDH2 * 2) + 128 * LDH2 * 2))    // 61440
#define SM_14 (3 * (2 * (64 * LDH2 * 2) + 64 * LDH2 * 2))     // 46080

// ================= conversion kernels =================
__global__ void split_weights(const float* W1, const float* H1, const float* W2,
                              const float* H2, const float* W3, const float* H3,
                              const float* W4,
                              f16* B1h, f16* B2h, f16* B3h, f16* B4h) {
    const float* src; f16* dh; int n, ntot;
    switch (blockIdx.y) {
        case 0: src = W1; dh = B1h;            n = 256*1024; ntot = n; break;
        case 1: src = H1; dh = B1h + 256*1024; n = 256*1024; ntot = n; break;
        case 2: src = W2; dh = B2h;            n = 128*256;  ntot = n; break;
        case 3: src = H2; dh = B2h + 128*256;  n = 128*256;  ntot = n; break;
        case 4: src = W3; dh = B3h;            n = 64*128;   ntot = n; break;
        case 5: src = H3; dh = B3h + 64*128;   n = 64*128;   ntot = n; break;
        default: src = W4; dh = B4h;           n = 1000*64;  ntot = 1024*64; break;
    }
    for (int i = (blockIdx.x * blockDim.x + threadIdx.x) * 4; i < ntot;
         i += gridDim.x * blockDim.x * 4) {
        float4 v;
        if (i + 3 < n) v = *reinterpret_cast<const float4*>(src + i);
        else v = make_float4(i < n ? src[i] : 0.f, i + 1 < n ? src[i + 1] : 0.f,
                             i + 2 < n ? src[i + 2] : 0.f, i + 3 < n ? src[i + 3] : 0.f);
        __half2 hp0, hp1;
        hp0.x = __float2half_rn(v.x); hp0.y = __float2half_rn(v.y);
        hp1.x = __float2half_rn(v.z); hp1.y = __float2half_rn(v.w);
        reinterpret_cast<__half2*>(dh + i)[0] = hp0;
        reinterpret_cast<__half2*>(dh + i)[1] = hp1;
    }
}

__global__ void rowstats_split(const float* __restrict__ X, float* __restrict__ invn,
                               float* __restrict__ rs, f16* __restrict__ xh,
                               f16* __restrict__ xl) {
    int b = blockIdx.x, t = threadIdx.x;   // 256 threads
    const float* row = X + (size_t)b * 1024;
    float4 v = *reinterpret_cast<const float4*>(row + t * 4);
    f16 h, l;
    __half2 hp0, hp1, lp0, lp1;
    split1(v.x, h, l); hp0.x = h; lp0.x = l;
    split1(v.y, h, l); hp0.y = h; lp0.y = l;
    split1(v.z, h, l); hp1.x = h; lp1.x = l;
    split1(v.w, h, l); hp1.y = h; lp1.y = l;
    size_t o = (size_t)b * 1024 + t * 4;
    reinterpret_cast<__half2*>(xh + o)[0] = hp0;
    reinterpret_cast<__half2*>(xh + o)[1] = hp1;
    reinterpret_cast<__half2*>(xl + o)[0] = lp0;
    reinterpret_cast<__half2*>(xl + o)[1] = lp1;
    float s = v.x + v.y + v.z + v.w;
    float ss = fmaf(v.x, v.x, fmaf(v.y, v.y, fmaf(v.z, v.z, v.w * v.w)));
    __shared__ float shs[8], shss[8];
    s = warp_sum(s); ss = warp_sum(ss);
    int w = t >> 5, lid = t & 31;
    if (lid == 0) { shs[w] = s; shss[w] = ss; }
    __syncthreads();
    if (t == 0) {
        float ts = 0.f, tss = 0.f;
#pragma unroll
        for (int i = 0; i < 8; i++) { ts += shs[i]; tss += shss[i]; }
        invn[b] = rsqrtf(tss);
        rs[b] = ts;
    }
}

__global__ void rowstats_hl(const f16* __restrict__ hi, const f16* __restrict__ lo,
                            int D, float* __restrict__ invn, float* __restrict__ rs) {
    int b = blockIdx.x, t = threadIdx.x;   // 128 threads
    float s = 0.f, ss = 0.f;
    for (int i = t; i < D; i += 128) {
        float v = __half2float(hi[(size_t)b * D + i]) +
                  __half2float(lo[(size_t)b * D + i]);
        s += v;
        ss = fmaf(v, v, ss);
    }
    __shared__ float shs[4], shss[4];
    s = warp_sum(s); ss = warp_sum(ss);
    int w = t >> 5, lid = t & 31;
    if (lid == 0) { shs[w] = s; shss[w] = ss; }
    __syncthreads();
    if (t == 0) {
        float ts = 0.f, tss = 0.f;
#pragma unroll
        for (int i = 0; i < 4; i++) { ts += shs[i]; tss += shss[i]; }
        invn[b] = rsqrtf(tss);
        rs[b] = ts;
    }
}

// ================= hebbian-path kernels =================
__global__ void cb_kernel(const float* __restrict__ T, int Y,
                          const float* __restrict__ invnx, const float* __restrict__ sb,
                          float* __restrict__ cb) {
    int wrp = (blockIdx.x * blockDim.x + threadIdx.x) >> 5;
    int lane = threadIdx.x & 31;
    if (wrp >= 8192) return;
    const float* row = T + (size_t)wrp * Y;
    float ss = 0.f;
    for (int i = lane; i < Y; i += 32) { float v = row[i]; ss = fmaf(v, v, ss); }
    ss = warp_sum(ss);
    if (lane == 0) cb[wrp] = sb[wrp] * invnx[wrp] * rsqrtf(ss);
}

__global__ void hebb_kernel(const float* __restrict__ T, int Y,
                            const float* __restrict__ cb, float* __restrict__ part) {
    int j = threadIdx.x;
    int b0 = blockIdx.x * 32;
    float a0 = 0.f, a1 = 0.f, a2 = 0.f, a3 = 0.f;
#pragma unroll
    for (int b = b0; b < b0 + 32; b += 4) {
        a0 = fmaf(T[(size_t)b * Y + j],       cb[b],     a0);
        a1 = fmaf(T[(size_t)(b + 1) * Y + j], cb[b + 1], a1);
        a2 = fmaf(T[(size_t)(b + 2) * Y + j], cb[b + 2], a2);
        a3 = fmaf(T[(size_t)(b + 3) * Y + j], cb[b + 3], a3);
    }
    part[blockIdx.x * Y + j] = (a0 + a1) + (a2 + a3);
}

__global__ void rowsum_kernel(const float* __restrict__ H, int D,
                              float* __restrict__ out) {
    int row = blockIdx.x, t = threadIdx.x;   // 128 threads
    float s = 0.f;
    for (int i = t; i < D; i += 128) s += H[(size_t)row * D + i];
    __shared__ float sh[4];
    s = warp_sum(s);
    if ((t & 31) == 0) sh[t >> 5] = s;
    __syncthreads();
    if (t == 0) out[row] = sh[0] + sh[1] + sh[2] + sh[3];
}

__global__ void score_kernel(const float* __restrict__ rsH, const float* __restrict__ part,
                             int Y, float* __restrict__ hm) {
    int j = threadIdx.x;
    float hb = 0.f;
    for (int p = 0; p < 256; p++) hb += part[p * Y + j];
    float theta = 1.0f / (float)Y;
    float sc = fmaf(1.0f - theta, rsH[j], hb);
    __shared__ float smin[256], smax[256];
    smin[j] = sc; smax[j] = sc;
    __syncthreads();
    for (int s = blockDim.x >> 1; s > 0; s >>= 1) {
        if (j < s) {
            smin[j] = fminf(smin[j], smin[j + s]);
            smax[j] = fmaxf(smax[j], smax[j + s]);
        }
        __syncthreads();
    }
    float mn = smin[0], mx = smax[0];
    float norm = (sc - mn) / (mx - mn + 1e-8f);
    hm[j] = (norm < 0.5f) ? 0.0f : 1.0f;
}

// ================= launcher (R12 schedule, repacked small GEMMs) ============
extern "C" void kernel_launch(void* const* d_in, const int* in_sizes, int n_in,
                              void* d_out, int out_size) {
    const float* x     = (const float*)d_in[0];
    const float* mask0 = (const float*)d_in[1];
    const float* mask1 = (const float*)d_in[2];
    const float* mask2 = (const float*)d_in[3];
    const float* W1 = (const float*)d_in[4];
    const float* b1 = (const float*)d_in[5];
    const float* W2 = (const float*)d_in[6];
    const float* b2 = (const float*)d_in[7];
    const float* W3 = (const float*)d_in[8];
    const float* b3 = (const float*)d_in[9];
    const float* W4 = (const float*)d_in[10];
    const float* b4 = (const float*)d_in[11];
    const float* H1 = (const float*)d_in[12];
    const float* H2 = (const float*)d_in[13];
    const float* H3 = (const float*)d_in[14];
    float* out = (float*)d_out;

    f16 *xh, *xl, *x1h, *x1l, *x2h, *x2l, *x3h, *x3l;
    f16 *B1h, *B2h, *B3h, *B4h;
    float *t1, *t2, *t3, *invn, *sbp, *cbp, *part1, *part2, *part3, *rsH;
    cudaGetSymbolAddress((void**)&xh, g_xh);   cudaGetSymbolAddress((void**)&xl, g_xl);
    cudaGetSymbolAddress((void**)&x1h, g_x1h); cudaGetSymbolAddress((void**)&x1l, g_x1l);
    cudaGetSymbolAddress((void**)&x2h, g_x2h); cudaGetSymbolAddress((void**)&x2l, g_x2l);
    cudaGetSymbolAddress((void**)&x3h, g_x3h); cudaGetSymbolAddress((void**)&x3l, g_x3l);
    cudaGetSymbolAddress((void**)&B1h, g_B1h);
    cudaGetSymbolAddress((void**)&B2h, g_B2h);
    cudaGetSymbolAddress((void**)&B3h, g_B3h);
    cudaGetSymbolAddress((void**)&B4h, g_B4h);
    cudaGetSymbolAddress((void**)&t1, g_t1);
    cudaGetSymbolAddress((void**)&t2, g_t2);
    cudaGetSymbolAddress((void**)&t3, g_t3);
    cudaGetSymbolAddress((void**)&invn, g_invn);
    cudaGetSymbolAddress((void**)&sbp, g_sb);
    cudaGetSymbolAddress((void**)&cbp, g_cb);
    cudaGetSymbolAddress((void**)&part1, g_part1);
    cudaGetSymbolAddress((void**)&part2, g_part2);
    cudaGetSymbolAddress((void**)&part3, g_part3);
    cudaGetSymbolAddress((void**)&rsH, g_rsH);

    float* invn1 = invn;        float* invn2 = invn + 8192;  float* invn3 = invn + 16384;
    float* sb1 = sbp;           float* sb2 = sbp + 8192;     float* sb3 = sbp + 16384;
    float* cb1 = cbp;           float* cb2 = cbp + 8192;     float* cb3 = cbp + 16384;

    static bool inited = false;
    static cudaStream_t s1, s2, s3;
    static cudaEvent_t eFork, eW, eR, eX, eG1, eG2, eG3, eS1, eS2, eS3;
    if (!inited) {
        cudaFuncSetAttribute(gemm_mma<2, 8>,
                             cudaFuncAttributeMaxDynamicSharedMemorySize, SM_28);
        cudaFuncSetAttribute(gemm_mma<1, 8>,
                             cudaFuncAttributeMaxDynamicSharedMemorySize, SM_18);
        cudaFuncSetAttribute(gemm_mma<1, 4>,
                             cudaFuncAttributeMaxDynamicSharedMemorySize, SM_14);
        int leastPri, greatestPri;
        cudaDeviceGetStreamPriorityRange(&leastPri, &greatestPri);
        cudaStreamCreateWithPriority(&s1, cudaStreamNonBlocking, leastPri);
        cudaStreamCreateWithPriority(&s2, cudaStreamNonBlocking, leastPri);
        cudaStreamCreateWithPriority(&s3, cudaStreamNonBlocking, leastPri);
        cudaEventCreateWithFlags(&eFork, cudaEventDisableTiming);
        cudaEventCreateWithFlags(&eW, cudaEventDisableTiming);
        cudaEventCreateWithFlags(&eR, cudaEventDisableTiming);
        cudaEventCreateWithFlags(&eX, cudaEventDisableTiming);
        cudaEventCreateWithFlags(&eG1, cudaEventDisableTiming);
        cudaEventCreateWithFlags(&eG2, cudaEventDisableTiming);
        cudaEventCreateWithFlags(&eG3, cudaEventDisableTiming);
        cudaEventCreateWithFlags(&eS1, cudaEventDisableTiming);
        cudaEventCreateWithFlags(&eS2, cudaEventDisableTiming);
        cudaEventCreateWithFlags(&eS3, cudaEventDisableTiming);
        inited = true;
    }

    const int B = 8192;
    const size_t OUT_OFF = (size_t)B * 1000;

    // ---- fork side streams off the capture stream ----
    cudaEventRecord(eFork, 0);
    cudaStreamWaitEvent(s1, eFork, 0);
    cudaStreamWaitEvent(s2, eFork, 0);
    cudaStreamWaitEvent(s3, eFork, 0);

    // s1: weight conversion (gates gemm1)
    split_weights<<<dim3(256, 7), 256, 0, s1>>>(W1, H1, W2, H2, W3, H3, W4,
                                                B1h, B2h, B3h, B4h);
    cudaEventRecord(eW, s1);

    // s2: H rowsums (score gates)
    rowsum_kernel<<<256, 128, 0, s2>>>(H1, 1024, rsH);
    rowsum_kernel<<<128, 128, 0, s2>>>(H2, 256, rsH + 256);
    rowsum_kernel<<<64, 128, 0, s2>>>(H3, 128, rsH + 384);
    cudaEventRecord(eR, s2);

    // s0: x conversion + stats
    rowstats_split<<<B, 256>>>(x, invn1, sb1, xh, xl);
    cudaEventRecord(eX, 0);

    // ======== critical GEMM chain on s0 (combined W+H tiles) ========
    cudaStreamWaitEvent(0, eW, 0);
    gemm_mma<2, 8><<<dim3(4, 64), 256, SM_28>>>(xh, xl, B1h, b1, mask0,
                                                x1h, x1l, nullptr, t1,
                                                1024, 256, 256);
    cudaEventRecord(eG1, 0);
    gemm_mma<1, 8><<<dim3(2, 128), 256, SM_18>>>(x1h, x1l, B2h, b2, mask1,
                                                 x2h, x2l, nullptr, t2,
                                                 256, 128, 128);
    cudaEventRecord(eG2, 0);
    gemm_mma<1, 4><<<dim3(2, 128), 256, SM_14>>>(x2h, x2l, B3h, b3, mask2,
                                                 x3h, x3l, nullptr, t3,
                                                 128, 64, 64);
    cudaEventRecord(eG3, 0);
    gemm_mma<2, 8><<<dim3(8, 64), 256, SM_28>>>(x3h, x3l, B4h, b4,
                                                (const float*)nullptr,
                                                (f16*)nullptr, (f16*)nullptr,
                                                out, (float*)nullptr,
                                                64, 1000, 0);

    // ======== layer-1 hebbian on s1 ========
    cudaStreamWaitEvent(s1, eG1, 0);
    cudaStreamWaitEvent(s1, eX, 0);
    cudaStreamWaitEvent(s1, eR, 0);
    cb_kernel<<<1024, 256, 0, s1>>>(t1, 256, invn1, sb1, cb1);
    hebb_kernel<<<256, 256, 0, s1>>>(t1, 256, cb1, part1);
    score_kernel<<<1, 256, 0, s1>>>(rsH, part1, 256, out + OUT_OFF);
    cudaEventRecord(eS1, s1);

    // ======== layer-2 hebbian on s2 ========
    cudaStreamWaitEvent(s2, eG1, 0);
    rowstats_hl<<<B, 128, 0, s2>>>(x1h, x1l, 256, invn2, sb2);
    cudaStreamWaitEvent(s2, eG2, 0);
    cb_kernel<<<1024, 256, 0, s2>>>(t2, 128, invn2, sb2, cb2);
    hebb_kernel<<<256, 128, 0, s2>>>(t2, 128, cb2, part2);
    score_kernel<<<1, 128, 0, s2>>>(rsH + 256, part2, 128, out + OUT_OFF + 256);
    cudaEventRecord(eS2, s2);

    // ======== layer-3 hebbian on s3 ========
    cudaStreamWaitEvent(s3, eG2, 0);
    rowstats_hl<<<B, 128, 0, s3>>>(x2h, x2l, 128, invn3, sb3);
    cudaStreamWaitEvent(s3, eG3, 0);
    cudaStreamWaitEvent(s3, eR, 0);
    cb_kernel<<<1024, 256, 0, s3>>>(t3, 64, invn3, sb3, cb3);
    hebb_kernel<<<256, 64, 0, s3>>>(t3, 64, cb3, part3);
    score_kernel<<<1, 64, 0, s3>>>(rsH + 384, part3, 64, out + OUT_OFF + 384);
    cudaEventRecord(eS3, s3);

    // ---- join ----
    cudaStreamWaitEvent(0, eS1, 0);
    cudaStreamWaitEvent(0, eS2, 0);
    cudaStreamWaitEvent(0, eS3, 0);
}

// round 15
// speedup vs baseline: 1.0864x; 1.0258x over previous
#include <cuda_runtime.h>
#include <cuda_fp16.h>
#include <cstdint>
#include <cstddef>

using f16 = __half;

// ================= device scratch (no allocations allowed) =================
__device__ __align__(16) f16 g_xh [8192 * 1024];
__device__ __align__(16) f16 g_xl [8192 * 1024];
__device__ __align__(16) f16 g_x1h[8192 * 256];
__device__ __align__(16) f16 g_x1l[8192 * 256];
__device__ __align__(16) f16 g_x2h[8192 * 128];
__device__ __align__(16) f16 g_x2l[8192 * 128];
__device__ __align__(16) f16 g_x3h[8192 * 64];
__device__ __align__(16) f16 g_x3l[8192 * 64];
__device__ __align__(16) f16 g_B1h[512 * 1024];
__device__ __align__(16) f16 g_B2h[256 * 256];
__device__ __align__(16) f16 g_B3h[128 * 128];
__device__ __align__(16) f16 g_B4h[1024 * 64];
__device__ float g_t1[8192 * 256];
__device__ float g_t2[8192 * 128];
__device__ float g_t3[8192 * 64];
__device__ float g_invn[3][8192];
__device__ float g_sb[3][8192];
__device__ float g_cb[3][8192];
__device__ float g_part1[256 * 256];
__device__ float g_part2[256 * 128];
__device__ float g_part3[256 * 64];
__device__ float g_rsH[512];          // slots: 0 / 256 / 384

// ================= helpers =================
__device__ __forceinline__ uint32_t smem_u32(const void* p) {
    uint32_t a;
    asm("{ .reg .u64 t; cvta.to.shared.u64 t, %1; cvt.u32.u64 %0, t; }"
        : "=r"(a) : "l"(p));
    return a;
}
__device__ __forceinline__ void ldsm4(uint32_t* r, uint32_t addr) {
    asm volatile("ldmatrix.sync.aligned.m8n8.x4.shared.b16 {%0,%1,%2,%3}, [%4];"
                 : "=r"(r[0]), "=r"(r[1]), "=r"(r[2]), "=r"(r[3]) : "r"(addr));
}
__device__ __forceinline__ void mma16816(float* d, const uint32_t* a, const uint32_t* b) {
    asm volatile(
        "mma.sync.aligned.m16n8k16.row.col.f32.f16.f16.f32 "
        "{%0,%1,%2,%3}, {%4,%5,%6,%7}, {%8,%9}, {%0,%1,%2,%3};"
        : "+f"(d[0]), "+f"(d[1]), "+f"(d[2]), "+f"(d[3])
        : "r"(a[0]), "r"(a[1]), "r"(a[2]), "r"(a[3]), "r"(b[0]), "r"(b[1]));
}
__device__ __forceinline__ void cp16(uint32_t dst, const void* src) {
    asm volatile("cp.async.cg.shared.global [%0], [%1], 16;"
                 :: "r"(dst), "l"(src) : "memory");
}
__device__ __forceinline__ void split1(float v, f16& h, f16& l) {
    h = __float2half_rn(v);
    l = __float2half_rn(v - __half2float(h));
}
__device__ __forceinline__ float warp_sum(float v) {
#pragma unroll
    for (int o = 16; o; o >>= 1) v += __shfl_down_sync(0xffffffffu, v, o);
    return v;
}

// ================= fp16 2-pass GEMM, KC=64 chunks, 2-stage =================
// D[m,n] = (Ah+Al)[m,:] . Bh[n,:]  via  Ah·Bh + Al·Bh
// MB = m-tiles(16) per warp (BM = 64*MB); NB = n-tiles(16) per CTA (BN = 16*NB).
#define LDH3 72                          // halfwords per row (64 + 8 pad)

template <int MB, int NB>
__global__ __launch_bounds__(256, 2)
void gemm_mma(const f16* __restrict__ Ah, const f16* __restrict__ Al,
              const f16* __restrict__ Bh,
              const float* __restrict__ bias, const float* __restrict__ mask,
              f16* __restrict__ Xh, f16* __restrict__ Xl,
              float* __restrict__ Xf, float* __restrict__ Tout,
              int K, int NW, int NT) {
    constexpr int BM = 64 * MB;
    constexpr int BN = 16 * NB;
    constexpr int TILE_A = BM * LDH3 * 2;      // one A buffer (Ah or Al)
    constexpr int TILE_Bb = BN * LDH3 * 2;
    constexpr int STG = 2 * TILE_A + TILE_Bb;
    extern __shared__ char smem[];
    const uint32_t sbase = smem_u32(smem);
    const int tid = threadIdx.x;
    const int lane = tid & 31;
    const int warp = tid >> 5;
    const int wm = warp >> 1;                  // 0..3
    const int wn = warp & 1;                   // 0..1
    const int bm = blockIdx.y * BM;
    const int bn = blockIdx.x * BN;
    const int NC = K >> 6;                     // chunks of 64

    const int row32 = tid >> 3;                // 0..31
    const int c8 = (tid & 7) * 8;              // halfword offset 0..56

    float acc[MB][NB][4];
#pragma unroll
    for (int i = 0; i < MB; i++)
#pragma unroll
        for (int j = 0; j < NB; j++)
#pragma unroll
            for (int q = 0; q < 4; q++) acc[i][j][q] = 0.f;

    auto issue = [&](int c, int buf) {
        int k0 = c << 6;
        uint32_t st = sbase + buf * STG;
#pragma unroll
        for (int i = 0; i < 2 * MB; i++) {     // A: BM rows, 32 per round
            int r = row32 + 32 * i;
            uint32_t off = (uint32_t)(r * LDH3 + c8) * 2;
            const size_t ao = (size_t)(bm + r) * K + k0 + c8;
            cp16(st + off, Ah + ao);
            cp16(st + TILE_A + off, Al + ao);
        }
#pragma unroll
        for (int i = 0; i < NB / 2; i++) {     // B: BN rows, 32 per round
            int r = row32 + 32 * i;
            uint32_t off = (uint32_t)(r * LDH3 + c8) * 2;
            const size_t bo = (size_t)(bn + r) * K + k0 + c8;
            cp16(st + 2 * TILE_A + off, Bh + bo);
        }
    };

    // prologue: fill up to 2 stages (one commit per slot, empties complete fast)
#pragma unroll
    for (int s = 0; s < 2; s++) {
        if (s < NC) issue(s, s);
        asm volatile("cp.async.commit_group;" ::: "memory");
    }

    const int rl = lane & 15, ka = (lane >> 4) * 8;
    const int sec = lane >> 3;
    const int nloc = ((sec & 2) ? 8 : 0) + (lane & 7);
    const int kb = (sec & 1) * 8;

    for (int c = 0; c < NC; c++) {
        asm volatile("cp.async.wait_group 1;" ::: "memory");
        __syncthreads();
        const uint32_t stb = sbase + (uint32_t)(c & 1) * STG;
#pragma unroll
        for (int kk = 0; kk < 64; kk += 16) {
            uint32_t ah[MB][4], al[MB][4];
#pragma unroll
            for (int i = 0; i < MB; i++) {
                uint32_t off =
                    (uint32_t)((wm * (MB * 16) + i * 16 + rl) * LDH3 + kk + ka) * 2;
                ldsm4(ah[i], stb + off);
                ldsm4(al[i], stb + TILE_A + off);
            }
            uint32_t b[NB][2];
#pragma unroll
            for (int p = 0; p < NB / 2; p++) {
                uint32_t r4[4];
                ldsm4(r4, stb + 2 * TILE_A +
                          (uint32_t)((wn * (NB * 8) + p * 16 + nloc) * LDH3 + kk + kb) * 2);
                b[2 * p][0] = r4[0]; b[2 * p][1] = r4[1];
                b[2 * p + 1][0] = r4[2]; b[2 * p + 1][1] = r4[3];
            }
#pragma unroll
            for (int i = 0; i < MB; i++)
#pragma unroll
                for (int j = 0; j < NB; j++) {
                    mma16816(acc[i][j], ah[i], b[j]);
                    mma16816(acc[i][j], al[i], b[j]);
                }
        }
        __syncthreads();
        if (c + 2 < NC) issue(c + 2, (c + 2) & 1);
        asm volatile("cp.async.commit_group;" ::: "memory");
    }

    // ---- epilogue ----
    const int rq = lane >> 2;
    const int cq = (lane & 3) * 2;
    const int Ntot = NW + NT;
#pragma unroll
    for (int i = 0; i < MB; i++) {
        int r0 = bm + wm * (MB * 16) + i * 16 + rq;
        int r1 = r0 + 8;
#pragma unroll
        for (int j = 0; j < NB; j++) {
            int c0 = bn + wn * (NB * 8) + j * 8 + cq;
            float v00 = acc[i][j][0], v01 = acc[i][j][1];
            float v10 = acc[i][j][2], v11 = acc[i][j][3];
            if (c0 < NW) {
                float bb0 = bias[c0], bb1 = bias[c0 + 1];
                v00 = fmaxf(v00 + bb0, 0.f); v01 = fmaxf(v01 + bb1, 0.f);
                v10 = fmaxf(v10 + bb0, 0.f); v11 = fmaxf(v11 + bb1, 0.f);
                if (mask) {
                    float m0 = mask[c0], m1 = mask[c0 + 1];
                    v00 *= m0; v01 *= m1; v10 *= m0; v11 *= m1;
                }
                if (Xh) {
                    f16 h, l;
                    __half2 hp, lp;
                    split1(v00, h, l); hp.x = h; lp.x = l;
                    split1(v01, h, l); hp.y = h; lp.y = l;
                    *reinterpret_cast<__half2*>(Xh + (size_t)r0 * NW + c0) = hp;
                    *reinterpret_cast<__half2*>(Xl + (size_t)r0 * NW + c0) = lp;
                    split1(v10, h, l); hp.x = h; lp.x = l;
                    split1(v11, h, l); hp.y = h; lp.y = l;
                    *reinterpret_cast<__half2*>(Xh + (size_t)r1 * NW + c0) = hp;
                    *reinterpret_cast<__half2*>(Xl + (size_t)r1 * NW + c0) = lp;
                } else {
                    *reinterpret_cast<float2*>(Xf + (size_t)r0 * NW + c0) =
                        make_float2(v00, v01);
                    *reinterpret_cast<float2*>(Xf + (size_t)r1 * NW + c0) =
                        make_float2(v10, v11);
                }
            } else if (c0 < Ntot) {
                int tc = c0 - NW;
                *reinterpret_cast<float2*>(Tout + (size_t)r0 * NT + tc) =
                    make_float2(v00, v01);
                *reinterpret_cast<float2*>(Tout + (size_t)r1 * NT + tc) =
                    make_float2(v10, v11);
            }
        }
    }
}

// smem sizes per instantiation (2 stages, KC=64)
#define SM_28 (2 * (2 * (128 * LDH3 * 2) + 128 * LDH3 * 2))   // 110592
#define SM_18 (2 * (2 * (64 * LDH3 * 2) + 128 * LDH3 * 2))    // 73728
#define SM_14 (2 * (2 * (64 * LDH3 * 2) + 64 * LDH3 * 2))     // 55296

// ================= conversion kernels =================
__global__ void split_weights(const float* W1, const float* H1, const float* W2,
                              const float* H2, const float* W3, const float* H3,
                              const float* W4,
                              f16* B1h, f16* B2h, f16* B3h, f16* B4h) {
    const float* src; f16* dh; int n, ntot;
    switch (blockIdx.y) {
        case 0: src = W1; dh = B1h;            n = 256*1024; ntot = n; break;
        case 1: src = H1; dh = B1h + 256*1024; n = 256*1024; ntot = n; break;
        case 2: src = W2; dh = B2h;            n = 128*256;  ntot = n; break;
        case 3: src = H2; dh = B2h + 128*256;  n = 128*256;  ntot = n; break;
        case 4: src = W3; dh = B3h;            n = 64*128;   ntot = n; break;
        case 5: src = H3; dh = B3h + 64*128;   n = 64*128;   ntot = n; break;
        default: src = W4; dh = B4h;           n = 1000*64;  ntot = 1024*64; break;
    }
    for (int i = (blockIdx.x * blockDim.x + threadIdx.x) * 4; i < ntot;
         i += gridDim.x * blockDim.x * 4) {
        float4 v;
        if (i + 3 < n) v = *reinterpret_cast<const float4*>(src + i);
        else v = make_float4(i < n ? src[i] : 0.f, i + 1 < n ? src[i + 1] : 0.f,
                             i + 2 < n ? src[i + 2] : 0.f, i + 3 < n ? src[i + 3] : 0.f);
        __half2 hp0, hp1;
        hp0.x = __float2half_rn(v.x); hp0.y = __float2half_rn(v.y);
        hp1.x = __float2half_rn(v.z); hp1.y = __float2half_rn(v.w);
        reinterpret_cast<__half2*>(dh + i)[0] = hp0;
        reinterpret_cast<__half2*>(dh + i)[1] = hp1;
    }
}

__global__ void rowstats_split(const float* __restrict__ X, float* __restrict__ invn,
                               float* __restrict__ rs, f16* __restrict__ xh,
                               f16* __restrict__ xl) {
    int b = blockIdx.x, t = threadIdx.x;   // 256 threads
    const float* row = X + (size_t)b * 1024;
    float4 v = *reinterpret_cast<const float4*>(row + t * 4);
    f16 h, l;
    __half2 hp0, hp1, lp0, lp1;
    split1(v.x, h, l); hp0.x = h; lp0.x = l;
    split1(v.y, h, l); hp0.y = h; lp0.y = l;
    split1(v.z, h, l); hp1.x = h; lp1.x = l;
    split1(v.w, h, l); hp1.y = h; lp1.y = l;
    size_t o = (size_t)b * 1024 + t * 4;
    reinterpret_cast<__half2*>(xh + o)[0] = hp0;
    reinterpret_cast<__half2*>(xh + o)[1] = hp1;
    reinterpret_cast<__half2*>(xl + o)[0] = lp0;
    reinterpret_cast<__half2*>(xl + o)[1] = lp1;
    float s = v.x + v.y + v.z + v.w;
    float ss = fmaf(v.x, v.x, fmaf(v.y, v.y, fmaf(v.z, v.z, v.w * v.w)));
    __shared__ float shs[8], shss[8];
    s = warp_sum(s); ss = warp_sum(ss);
    int w = t >> 5, lid = t & 31;
    if (lid == 0) { shs[w] = s; shss[w] = ss; }
    __syncthreads();
    if (t == 0) {
        float ts = 0.f, tss = 0.f;
#pragma unroll
        for (int i = 0; i < 8; i++) { ts += shs[i]; tss += shss[i]; }
        invn[b] = rsqrtf(tss);
        rs[b] = ts;
    }
}

__global__ void rowstats_hl(const f16* __restrict__ hi, const f16* __restrict__ lo,
                            int D, float* __restrict__ invn, float* __restrict__ rs) {
    int b = blockIdx.x, t = threadIdx.x;   // 128 threads
    float s = 0.f, ss = 0.f;
    for (int i = t; i < D; i += 128) {
        float v = __half2float(hi[(size_t)b * D + i]) +
                  __half2float(lo[(size_t)b * D + i]);
        s += v;
        ss = fmaf(v, v, ss);
    }
    __shared__ float shs[4], shss[4];
    s = warp_sum(s); ss = warp_sum(ss);
    int w = t >> 5, lid = t & 31;
    if (lid == 0) { shs[w] = s; shss[w] = ss; }
    __syncthreads();
    if (t == 0) {
        float ts = 0.f, tss = 0.f;
#pragma unroll
        for (int i = 0; i < 4; i++) { ts += shs[i]; tss += shss[i]; }
        invn[b] = rsqrtf(tss);
        rs[b] = ts;
    }
}

// ================= hebbian-path kernels =================
__global__ void cb_kernel(const float* __restrict__ T, int Y,
                          const float* __restrict__ invnx, const float* __restrict__ sb,
                          float* __restrict__ cb) {
    int wrp = (blockIdx.x * blockDim.x + threadIdx.x) >> 5;
    int lane = threadIdx.x & 31;
    if (wrp >= 8192) return;
    const float* row = T + (size_t)wrp * Y;
    float ss = 0.f;
    for (int i = lane; i < Y; i += 32) { float v = row[i]; ss = fmaf(v, v, ss); }
    ss = warp_sum(ss);
    if (lane == 0) cb[wrp] = sb[wrp] * invnx[wrp] * rsqrtf(ss);
}

__global__ void hebb_kernel(const float* __restrict__ T, int Y,
                            const float* __restrict__ cb, float* __restrict__ part) {
    int j = threadIdx.x;
    int b0 = blockIdx.x * 32;
    float a0 = 0.f, a1 = 0.f, a2 = 0.f, a3 = 0.f;
#pragma unroll
    for (int b = b0; b < b0 + 32; b += 4) {
        a0 = fmaf(T[(size_t)b * Y + j],       cb[b],     a0);
        a1 = fmaf(T[(size_t)(b + 1) * Y + j], cb[b + 1], a1);
        a2 = fmaf(T[(size_t)(b + 2) * Y + j], cb[b + 2], a2);
        a3 = fmaf(T[(size_t)(b + 3) * Y + j], cb[b + 3], a3);
    }
    part[blockIdx.x * Y + j] = (a0 + a1) + (a2 + a3);
}

__global__ void rowsum_kernel(const float* __restrict__ H, int D,
                              float* __restrict__ out) {
    int row = blockIdx.x, t = threadIdx.x;   // 128 threads
    float s = 0.f;
    for (int i = t; i < D; i += 128) s += H[(size_t)row * D + i];
    __shared__ float sh[4];
    s = warp_sum(s);
    if ((t & 31) == 0) sh[t >> 5] = s;
    __syncthreads();
    if (t == 0) out[row] = sh[0] + sh[1] + sh[2] + sh[3];
}

__global__ void score_kernel(const float* __restrict__ rsH, const float* __restrict__ part,
                             int Y, float* __restrict__ hm) {
    int j = threadIdx.x;
    float hb = 0.f;
    for (int p = 0; p < 256; p++) hb += part[p * Y + j];
    float theta = 1.0f / (float)Y;
    float sc = fmaf(1.0f - theta, rsH[j], hb);
    __shared__ float smin[256], smax[256];
    smin[j] = sc; smax[j] = sc;
    __syncthreads();
    for (int s = blockDim.x >> 1; s > 0; s >>= 1) {
        if (j < s) {
            smin[j] = fminf(smin[j], smin[j + s]);
            smax[j] = fmaxf(smax[j], smax[j + s]);
        }
        __syncthreads();
    }
    float mn = smin[0], mx = smax[0];
    float norm = (sc - mn) / (mx - mn + 1e-8f);
    hm[j] = (norm < 0.5f) ? 0.0f : 1.0f;
}

// ================= launcher (R14 schedule) =================
extern "C" void kernel_launch(void* const* d_in, const int* in_sizes, int n_in,
                              void* d_out, int out_size) {
    const float* x     = (const float*)d_in[0];
    const float* mask0 = (const float*)d_in[1];
    const float* mask1 = (const float*)d_in[2];
    const float* mask2 = (const float*)d_in[3];
    const float* W1 = (const float*)d_in[4];
    const float* b1 = (const float*)d_in[5];
    const float* W2 = (const float*)d_in[6];
    const float* b2 = (const float*)d_in[7];
    const float* W3 = (const float*)d_in[8];
    const float* b3 = (const float*)d_in[9];
    const float* W4 = (const float*)d_in[10];
    const float* b4 = (const float*)d_in[11];
    const float* H1 = (const float*)d_in[12];
    const float* H2 = (const float*)d_in[13];
    const float* H3 = (const float*)d_in[14];
    float* out = (float*)d_out;

    f16 *xh, *xl, *x1h, *x1l, *x2h, *x2l, *x3h, *x3l;
    f16 *B1h, *B2h, *B3h, *B4h;
    float *t1, *t2, *t3, *invn, *sbp, *cbp, *part1, *part2, *part3, *rsH;
    cudaGetSymbolAddress((void**)&xh, g_xh);   cudaGetSymbolAddress((void**)&xl, g_xl);
    cudaGetSymbolAddress((void**)&x1h, g_x1h); cudaGetSymbolAddress((void**)&x1l, g_x1l);
    cudaGetSymbolAddress((void**)&x2h, g_x2h); cudaGetSymbolAddress((void**)&x2l, g_x2l);
    cudaGetSymbolAddress((void**)&x3h, g_x3h); cudaGetSymbolAddress((void**)&x3l, g_x3l);
    cudaGetSymbolAddress((void**)&B1h, g_B1h);
    cudaGetSymbolAddress((void**)&B2h, g_B2h);
    cudaGetSymbolAddress((void**)&B3h, g_B3h);
    cudaGetSymbolAddress((void**)&B4h, g_B4h);
    cudaGetSymbolAddress((void**)&t1, g_t1);
    cudaGetSymbolAddress((void**)&t2, g_t2);
    cudaGetSymbolAddress((void**)&t3, g_t3);
    cudaGetSymbolAddress((void**)&invn, g_invn);
    cudaGetSymbolAddress((void**)&sbp, g_sb);
    cudaGetSymbolAddress((void**)&cbp, g_cb);
    cudaGetSymbolAddress((void**)&part1, g_part1);
    cudaGetSymbolAddress((void**)&part2, g_part2);
    cudaGetSymbolAddress((void**)&part3, g_part3);
    cudaGetSymbolAddress((void**)&rsH, g_rsH);

    float* invn1 = invn;        float* invn2 = invn + 8192;  float* invn3 = invn + 16384;
    float* sb1 = sbp;           float* sb2 = sbp + 8192;     float* sb3 = sbp + 16384;
    float* cb1 = cbp;           float* cb2 = cbp + 8192;     float* cb3 = cbp + 16384;

    static bool inited = false;
    static cudaStream_t s1, s2, s3;
    static cudaEvent_t eFork, eW, eR, eX, eG1, eG2, eG3, eS1, eS2, eS3;
    if (!inited) {
        cudaFuncSetAttribute(gemm_mma<2, 8>,
                             cudaFuncAttributeMaxDynamicSharedMemorySize, SM_28);
        cudaFuncSetAttribute(gemm_mma<1, 8>,
                             cudaFuncAttributeMaxDynamicSharedMemorySize, SM_18);
        cudaFuncSetAttribute(gemm_mma<1, 4>,
                             cudaFuncAttributeMaxDynamicSharedMemorySize, SM_14);
        int leastPri, greatestPri;
        cudaDeviceGetStreamPriorityRange(&leastPri, &greatestPri);
        cudaStreamCreateWithPriority(&s1, cudaStreamNonBlocking, leastPri);
        cudaStreamCreateWithPriority(&s2, cudaStreamNonBlocking, leastPri);
        cudaStreamCreateWithPriority(&s3, cudaStreamNonBlocking, leastPri);
        cudaEventCreateWithFlags(&eFork, cudaEventDisableTiming);
        cudaEventCreateWithFlags(&eW, cudaEventDisableTiming);
        cudaEventCreateWithFlags(&eR, cudaEventDisableTiming);
        cudaEventCreateWithFlags(&eX, cudaEventDisableTiming);
        cudaEventCreateWithFlags(&eG1, cudaEventDisableTiming);
        cudaEventCreateWithFlags(&eG2, cudaEventDisableTiming);
        cudaEventCreateWithFlags(&eG3, cudaEventDisableTiming);
        cudaEventCreateWithFlags(&eS1, cudaEventDisableTiming);
        cudaEventCreateWithFlags(&eS2, cudaEventDisableTiming);
        cudaEventCreateWithFlags(&eS3, cudaEventDisableTiming);
        inited = true;
    }

    const int B = 8192;
    const size_t OUT_OFF = (size_t)B * 1000;

    // ---- fork side streams off the capture stream ----
    cudaEventRecord(eFork, 0);
    cudaStreamWaitEvent(s1, eFork, 0);
    cudaStreamWaitEvent(s2, eFork, 0);
    cudaStreamWaitEvent(s3, eFork, 0);

    // s1: weight conversion (gates gemm1)
    split_weights<<<dim3(256, 7), 256, 0, s1>>>(W1, H1, W2, H2, W3, H3, W4,
                                                B1h, B2h, B3h, B4h);
    cudaEventRecord(eW, s1);

    // s2: H rowsums (score gates)
    rowsum_kernel<<<256, 128, 0, s2>>>(H1, 1024, rsH);
    rowsum_kernel<<<128, 128, 0, s2>>>(H2, 256, rsH + 256);
    rowsum_kernel<<<64, 128, 0, s2>>>(H3, 128, rsH + 384);
    cudaEventRecord(eR, s2);

    // s0: x conversion + stats
    rowstats_split<<<B, 256>>>(x, invn1, sb1, xh, xl);
    cudaEventRecord(eX, 0);

    // ======== critical GEMM chain on s0 (combined W+H tiles) ========
    cudaStreamWaitEvent(0, eW, 0);
    gemm_mma<2, 8><<<dim3(4, 64), 256, SM_28>>>(xh, xl, B1h, b1, mask0,
                                                x1h, x1l, nullptr, t1,
                                                1024, 256, 256);
    cudaEventRecord(eG1, 0);
    gemm_mma<1, 8><<<dim3(2, 128), 256, SM_18>>>(x1h, x1l, B2h, b2, mask1,
                                                 x2h, x2l, nullptr, t2,
                                                 256, 128, 128);
    cudaEventRecord(eG2, 0);
    gemm_mma<1, 4><<<dim3(2, 128), 256, SM_14>>>(x2h, x2l, B3h, b3, mask2,
                                                 x3h, x3l, nullptr, t3,
                                                 128, 64, 64);
    cudaEventRecord(eG3, 0);
    gemm_mma<2, 8><<<dim3(8, 64), 256, SM_28>>>(x3h, x3l, B4h, b4,
                                                (const float*)nullptr,
                                                (f16*)nullptr, (f16*)nullptr,
                                                out, (float*)nullptr,
                                                64, 1000, 0);

    // ======== layer-1 hebbian on s1 ========
    cudaStreamWaitEvent(s1, eG1, 0);
    cudaStreamWaitEvent(s1, eX, 0);
    cudaStreamWaitEvent(s1, eR, 0);
    cb_kernel<<<1024, 256, 0, s1>>>(t1, 256, invn1, sb1, cb1);
    hebb_kernel<<<256, 256, 0, s1>>>(t1, 256, cb1, part1);
    score_kernel<<<1, 256, 0, s1>>>(rsH, part1, 256, out + OUT_OFF);
    cudaEventRecord(eS1, s1);

    // ======== layer-2 hebbian on s2 ========
    cudaStreamWaitEvent(s2, eG1, 0);
    rowstats_hl<<<B, 128, 0, s2>>>(x1h, x1l, 256, invn2, sb2);
    cudaStreamWaitEvent(s2, eG2, 0);
    cb_kernel<<<1024, 256, 0, s2>>>(t2, 128, invn2, sb2, cb2);
    hebb_kernel<<<256, 128, 0, s2>>>(t2, 128, cb2, part2);
    score_kernel<<<1, 128, 0, s2>>>(rsH + 256, part2, 128, out + OUT_OFF + 256);
    cudaEventRecord(eS2, s2);

    // ======== layer-3 hebbian on s3 ========
    cudaStreamWaitEvent(s3, eG2, 0);
    rowstats_hl<<<B, 128, 0, s3>>>(x2h, x2l, 128, invn3, sb3);
    cudaStreamWaitEvent(s3, eG3, 0);
    cudaStreamWaitEvent(s3, eR, 0);
    cb_kernel<<<1024, 256, 0, s3>>>(t3, 64, invn3, sb3, cb3);
    hebb_kernel<<<256, 64, 0, s3>>>(t3, 64, cb3, part3);
    score_kernel<<<1, 64, 0, s3>>>(rsH + 384, part3, 64, out + OUT_OFF + 384);
    cudaEventRecord(eS3, s3);

    // ---- join ----
    cudaStreamWaitEvent(0, eS1, 0);
    cudaStreamWaitEvent(0, eS2, 0);
    cudaStreamWaitEvent(0, eS3, 0);
}

// round 16
// speedup vs baseline: 1.1320x; 1.0420x over previous
#include <cuda_runtime.h>
#include <cuda_fp16.h>
#include <cstdint>
#include <cstddef>

using f16 = __half;

// ================= device scratch (no allocations allowed) =================
__device__ __align__(16) f16 g_xh [8192 * 1024];
__device__ __align__(16) f16 g_xl [8192 * 1024];
__device__ __align__(16) f16 g_x1h[8192 * 256];
__device__ __align__(16) f16 g_x1l[8192 * 256];
__device__ __align__(16) f16 g_x2h[8192 * 128];
__device__ __align__(16) f16 g_x2l[8192 * 128];
__device__ __align__(16) f16 g_x3h[8192 * 64];
__device__ __align__(16) f16 g_x3l[8192 * 64];
__device__ __align__(16) f16 g_B1h[512 * 1024];
__device__ __align__(16) f16 g_B2h[256 * 256];
__device__ __align__(16) f16 g_B3h[128 * 128];
__device__ __align__(16) f16 g_B4h[1024 * 64];
__device__ float g_t1[8192 * 256];
__device__ float g_t2[8192 * 128];
__device__ float g_t3[8192 * 64];
__device__ float g_invn[3][8192];
__device__ float g_sb[3][8192];
__device__ float g_cb[3][8192];
__device__ float g_part1[256 * 256];
__device__ float g_part2[256 * 128];
__device__ float g_part3[256 * 64];
__device__ float g_rsH[512];          // slots: 0 / 256 / 384

// ================= helpers =================
__device__ __forceinline__ uint32_t smem_u32(const void* p) {
    uint32_t a;
    asm("{ .reg .u64 t; cvta.to.shared.u64 t, %1; cvt.u32.u64 %0, t; }"
        : "=r"(a) : "l"(p));
    return a;
}
__device__ __forceinline__ void ldsm4(uint32_t* r, uint32_t addr) {
    asm volatile("ldmatrix.sync.aligned.m8n8.x4.shared.b16 {%0,%1,%2,%3}, [%4];"
                 : "=r"(r[0]), "=r"(r[1]), "=r"(r[2]), "=r"(r[3]) : "r"(addr));
}
__device__ __forceinline__ void mma16816(float* d, const uint32_t* a, const uint32_t* b) {
    asm volatile(
        "mma.sync.aligned.m16n8k16.row.col.f32.f16.f16.f32 "
        "{%0,%1,%2,%3}, {%4,%5,%6,%7}, {%8,%9}, {%0,%1,%2,%3};"
        : "+f"(d[0]), "+f"(d[1]), "+f"(d[2]), "+f"(d[3])
        : "r"(a[0]), "r"(a[1]), "r"(a[2]), "r"(a[3]), "r"(b[0]), "r"(b[1]));
}
__device__ __forceinline__ void cp16(uint32_t dst, const void* src) {
    asm volatile("cp.async.cg.shared.global [%0], [%1], 16;"
                 :: "r"(dst), "l"(src) : "memory");
}
__device__ __forceinline__ void split1(float v, f16& h, f16& l) {
    h = __float2half_rn(v);
    l = __float2half_rn(v - __half2float(h));
}
__device__ __forceinline__ float warp_sum(float v) {
#pragma unroll
    for (int o = 16; o; o >>= 1) v += __shfl_down_sync(0xffffffffu, v, o);
    return v;
}

// ================= fp16 2-pass GEMM, KC=64 chunks, 2-stage, unrolled NC =====
// D[m,n] = (Ah+Al)[m,:] . Bh[n,:]  via  Ah·Bh + Al·Bh
// MB = m-tiles(16) per warp (BM = 64*MB); NB = n-tiles(8) per warp (BN = 16*NB).
// NCc = compile-time chunk count (K = 64*NCc).
#define LDH3 72                          // halfwords per row (64 + 8 pad)

template <int MB, int NB, int NCc>
__global__ __launch_bounds__(256, 2)
void gemm_mma(const f16* __restrict__ Ah, const f16* __restrict__ Al,
              const f16* __restrict__ Bh,
              const float* __restrict__ bias, const float* __restrict__ mask,
              f16* __restrict__ Xh, f16* __restrict__ Xl,
              float* __restrict__ Xf, float* __restrict__ Tout,
              int NW, int NT) {
    constexpr int K = 64 * NCc;
    constexpr int BM = 64 * MB;
    constexpr int BN = 16 * NB;
    constexpr int TILE_A = BM * LDH3 * 2;      // one A buffer (Ah or Al)
    constexpr int TILE_Bb = BN * LDH3 * 2;
    constexpr int STG = 2 * TILE_A + TILE_Bb;
    extern __shared__ char smem[];
    const uint32_t sbase = smem_u32(smem);
    const int tid = threadIdx.x;
    const int lane = tid & 31;
    const int warp = tid >> 5;
    const int wm = warp >> 1;                  // 0..3
    const int wn = warp & 1;                   // 0..1
    const int bm = blockIdx.y * BM;
    const int bn = blockIdx.x * BN;

    const int row32 = tid >> 3;                // 0..31
    const int c8 = (tid & 7) * 8;              // halfword offset 0..56

    float acc[MB][NB][4];
#pragma unroll
    for (int i = 0; i < MB; i++)
#pragma unroll
        for (int j = 0; j < NB; j++)
#pragma unroll
            for (int q = 0; q < 4; q++) acc[i][j][q] = 0.f;

    auto issue = [&](int c, int buf) {
        int k0 = c << 6;
        uint32_t st = sbase + buf * STG;
#pragma unroll
        for (int i = 0; i < 2 * MB; i++) {     // A: BM rows, 32 per round
            int r = row32 + 32 * i;
            uint32_t off = (uint32_t)(r * LDH3 + c8) * 2;
            const size_t ao = (size_t)(bm + r) * K + k0 + c8;
            cp16(st + off, Ah + ao);
            cp16(st + TILE_A + off, Al + ao);
        }
#pragma unroll
        for (int i = 0; i < NB / 2; i++) {     // B: BN rows, 32 per round
            int r = row32 + 32 * i;
            uint32_t off = (uint32_t)(r * LDH3 + c8) * 2;
            const size_t bo = (size_t)(bn + r) * K + k0 + c8;
            cp16(st + 2 * TILE_A + off, Bh + bo);
        }
    };

    // prologue: fill up to 2 stages (one commit per slot, empties complete fast)
#pragma unroll
    for (int s = 0; s < 2; s++) {
        if (s < NCc) issue(s, s);
        asm volatile("cp.async.commit_group;" ::: "memory");
    }

    const int rl = lane & 15, ka = (lane >> 4) * 8;
    const int sec = lane >> 3;
    const int nloc = ((sec & 2) ? 8 : 0) + (lane & 7);
    const int kb = (sec & 1) * 8;

#pragma unroll
    for (int c = 0; c < NCc; c++) {
        asm volatile("cp.async.wait_group 1;" ::: "memory");
        __syncthreads();
        const uint32_t stb = sbase + (uint32_t)(c & 1) * STG;
#pragma unroll
        for (int kk = 0; kk < 64; kk += 16) {
            uint32_t ah[MB][4], al[MB][4];
#pragma unroll
            for (int i = 0; i < MB; i++) {
                uint32_t off =
                    (uint32_t)((wm * (MB * 16) + i * 16 + rl) * LDH3 + kk + ka) * 2;
                ldsm4(ah[i], stb + off);
                ldsm4(al[i], stb + TILE_A + off);
            }
            uint32_t b[NB][2];
#pragma unroll
            for (int p = 0; p < NB / 2; p++) {
                uint32_t r4[4];
                ldsm4(r4, stb + 2 * TILE_A +
                          (uint32_t)((wn * (NB * 8) + p * 16 + nloc) * LDH3 + kk + kb) * 2);
                b[2 * p][0] = r4[0]; b[2 * p][1] = r4[1];
                b[2 * p + 1][0] = r4[2]; b[2 * p + 1][1] = r4[3];
            }
#pragma unroll
            for (int i = 0; i < MB; i++)
#pragma unroll
                for (int j = 0; j < NB; j++) {
                    mma16816(acc[i][j], ah[i], b[j]);
                    mma16816(acc[i][j], al[i], b[j]);
                }
        }
        __syncthreads();
        if (c + 2 < NCc) issue(c + 2, (c + 2) & 1);
        asm volatile("cp.async.commit_group;" ::: "memory");
    }

    // ---- epilogue ----
    const int rq = lane >> 2;
    const int cq = (lane & 3) * 2;
    const int Ntot = NW + NT;
#pragma unroll
    for (int i = 0; i < MB; i++) {
        int r0 = bm + wm * (MB * 16) + i * 16 + rq;
        int r1 = r0 + 8;
#pragma unroll
        for (int j = 0; j < NB; j++) {
            int c0 = bn + wn * (NB * 8) + j * 8 + cq;
            float v00 = acc[i][j][0], v01 = acc[i][j][1];
            float v10 = acc[i][j][2], v11 = acc[i][j][3];
            if (c0 < NW) {
                float bb0 = bias[c0], bb1 = bias[c0 + 1];
                v00 = fmaxf(v00 + bb0, 0.f); v01 = fmaxf(v01 + bb1, 0.f);
                v10 = fmaxf(v10 + bb0, 0.f); v11 = fmaxf(v11 + bb1, 0.f);
                if (mask) {
                    float m0 = mask[c0], m1 = mask[c0 + 1];
                    v00 *= m0; v01 *= m1; v10 *= m0; v11 *= m1;
                }
                if (Xh) {
                    f16 h, l;
                    __half2 hp, lp;
                    split1(v00, h, l); hp.x = h; lp.x = l;
                    split1(v01, h, l); hp.y = h; lp.y = l;
                    *reinterpret_cast<__half2*>(Xh + (size_t)r0 * NW + c0) = hp;
                    *reinterpret_cast<__half2*>(Xl + (size_t)r0 * NW + c0) = lp;
                    split1(v10, h, l); hp.x = h; lp.x = l;
                    split1(v11, h, l); hp.y = h; lp.y = l;
                    *reinterpret_cast<__half2*>(Xh + (size_t)r1 * NW + c0) = hp;
                    *reinterpret_cast<__half2*>(Xl + (size_t)r1 * NW + c0) = lp;
                } else {
                    *reinterpret_cast<float2*>(Xf + (size_t)r0 * NW + c0) =
                        make_float2(v00, v01);
                    *reinterpret_cast<float2*>(Xf + (size_t)r1 * NW + c0) =
                        make_float2(v10, v11);
                }
            } else if (c0 < Ntot) {
                int tc = c0 - NW;
                *reinterpret_cast<float2*>(Tout + (size_t)r0 * NT + tc) =
                    make_float2(v00, v01);
                *reinterpret_cast<float2*>(Tout + (size_t)r1 * NT + tc) =
                    make_float2(v10, v11);
            }
        }
    }
}

// smem sizes per instantiation (2 stages, KC=64)
#define SM_28 (2 * (2 * (128 * LDH3 * 2) + 128 * LDH3 * 2))   // 110592
#define SM_18 (2 * (2 * (64 * LDH3 * 2) + 128 * LDH3 * 2))    // 73728
#define SM_14 (2 * (2 * (64 * LDH3 * 2) + 64 * LDH3 * 2))     // 55296

// ================= conversion kernels =================
__global__ void split_weights(const float* W1, const float* H1, const float* W2,
                              const float* H2, const float* W3, const float* H3,
                              const float* W4,
                              f16* B1h, f16* B2h, f16* B3h, f16* B4h) {
    const float* src; f16* dh; int n, ntot;
    switch (blockIdx.y) {
        case 0: src = W1; dh = B1h;            n = 256*1024; ntot = n; break;
        case 1: src = H1; dh = B1h + 256*1024; n = 256*1024; ntot = n; break;
        case 2: src = W2; dh = B2h;            n = 128*256;  ntot = n; break;
        case 3: src = H2; dh = B2h + 128*256;  n = 128*256;  ntot = n; break;
        case 4: src = W3; dh = B3h;            n = 64*128;   ntot = n; break;
        case 5: src = H3; dh = B3h + 64*128;   n = 64*128;   ntot = n; break;
        default: src = W4; dh = B4h;           n = 1000*64;  ntot = 1024*64; break;
    }
    for (int i = (blockIdx.x * blockDim.x + threadIdx.x) * 4; i < ntot;
         i += gridDim.x * blockDim.x * 4) {
        float4 v;
        if (i + 3 < n) v = *reinterpret_cast<const float4*>(src + i);
        else v = make_float4(i < n ? src[i] : 0.f, i + 1 < n ? src[i + 1] : 0.f,
                             i + 2 < n ? src[i + 2] : 0.f, i + 3 < n ? src[i + 3] : 0.f);
        __half2 hp0, hp1;
        hp0.x = __float2half_rn(v.x); hp0.y = __float2half_rn(v.y);
        hp1.x = __float2half_rn(v.z); hp1.y = __float2half_rn(v.w);
        reinterpret_cast<__half2*>(dh + i)[0] = hp0;
        reinterpret_cast<__half2*>(dh + i)[1] = hp1;
    }
}

__global__ void rowstats_split(const float* __restrict__ X, float* __restrict__ invn,
                               float* __restrict__ rs, f16* __restrict__ xh,
                               f16* __restrict__ xl) {
    int b = blockIdx.x, t = threadIdx.x;   // 256 threads
    const float* row = X + (size_t)b * 1024;
    float4 v = *reinterpret_cast<const float4*>(row + t * 4);
    f16 h, l;
    __half2 hp0, hp1, lp0, lp1;
    split1(v.x, h, l); hp0.x = h; lp0.x = l;
    split1(v.y, h, l); hp0.y = h; lp0.y = l;
    split1(v.z, h, l); hp1.x = h; lp1.x = l;
    split1(v.w, h, l); hp1.y = h; lp1.y = l;
    size_t o = (size_t)b * 1024 + t * 4;
    reinterpret_cast<__half2*>(xh + o)[0] = hp0;
    reinterpret_cast<__half2*>(xh + o)[1] = hp1;
    reinterpret_cast<__half2*>(xl + o)[0] = lp0;
    reinterpret_cast<__half2*>(xl + o)[1] = lp1;
    float s = v.x + v.y + v.z + v.w;
    float ss = fmaf(v.x, v.x, fmaf(v.y, v.y, fmaf(v.z, v.z, v.w * v.w)));
    __shared__ float shs[8], shss[8];
    s = warp_sum(s); ss = warp_sum(ss);
    int w = t >> 5, lid = t & 31;
    if (lid == 0) { shs[w] = s; shss[w] = ss; }
    __syncthreads();
    if (t == 0) {
        float ts = 0.f, tss = 0.f;
#pragma unroll
        for (int i = 0; i < 8; i++) { ts += shs[i]; tss += shss[i]; }
        invn[b] = rsqrtf(tss);
        rs[b] = ts;
    }
}

__global__ void rowstats_hl(const f16* __restrict__ hi, const f16* __restrict__ lo,
                            int D, float* __restrict__ invn, float* __restrict__ rs) {
    int b = blockIdx.x, t = threadIdx.x;   // 128 threads
    float s = 0.f, ss = 0.f;
    for (int i = t; i < D; i += 128) {
        float v = __half2float(hi[(size_t)b * D + i]) +
                  __half2float(lo[(size_t)b * D + i]);
        s += v;
        ss = fmaf(v, v, ss);
    }
    __shared__ float shs[4], shss[4];
    s = warp_sum(s); ss = warp_sum(ss);
    int w = t >> 5, lid = t & 31;
    if (lid == 0) { shs[w] = s; shss[w] = ss; }
    __syncthreads();
    if (t == 0) {
        float ts = 0.f, tss = 0.f;
#pragma unroll
        for (int i = 0; i < 4; i++) { ts += shs[i]; tss += shss[i]; }
        invn[b] = rsqrtf(tss);
        rs[b] = ts;
    }
}

// ================= hebbian-path kernels =================
__global__ void cb_kernel(const float* __restrict__ T, int Y,
                          const float* __restrict__ invnx, const float* __restrict__ sb,
                          float* __restrict__ cb) {
    int wrp = (blockIdx.x * blockDim.x + threadIdx.x) >> 5;
    int lane = threadIdx.x & 31;
    if (wrp >= 8192) return;
    const float* row = T + (size_t)wrp * Y;
    float ss = 0.f;
    for (int i = lane; i < Y; i += 32) { float v = row[i]; ss = fmaf(v, v, ss); }
    ss = warp_sum(ss);
    if (lane == 0) cb[wrp] = sb[wrp] * invnx[wrp] * rsqrtf(ss);
}

__global__ void hebb_kernel(const float* __restrict__ T, int Y,
                            const float* __restrict__ cb, float* __restrict__ part) {
    int j = threadIdx.x;
    int b0 = blockIdx.x * 32;
    float a0 = 0.f, a1 = 0.f, a2 = 0.f, a3 = 0.f;
#pragma unroll
    for (int b = b0; b < b0 + 32; b += 4) {
        a0 = fmaf(T[(size_t)b * Y + j],       cb[b],     a0);
        a1 = fmaf(T[(size_t)(b + 1) * Y + j], cb[b + 1], a1);
        a2 = fmaf(T[(size_t)(b + 2) * Y + j], cb[b + 2], a2);
        a3 = fmaf(T[(size_t)(b + 3) * Y + j], cb[b + 3], a3);
    }
    part[blockIdx.x * Y + j] = (a0 + a1) + (a2 + a3);
}

__global__ void rowsum_kernel(const float* __restrict__ H, int D,
                              float* __restrict__ out) {
    int row = blockIdx.x, t = threadIdx.x;   // 128 threads
    float s = 0.f;
    for (int i = t; i < D; i += 128) s += H[(size_t)row * D + i];
    __shared__ float sh[4];
    s = warp_sum(s);
    if ((t & 31) == 0) sh[t >> 5] = s;
    __syncthreads();
    if (t == 0) out[row] = sh[0] + sh[1] + sh[2] + sh[3];
}

__global__ void score_kernel(const float* __restrict__ rsH, const float* __restrict__ part,
                             int Y, float* __restrict__ hm) {
    int j = threadIdx.x;
    float hb = 0.f;
    for (int p = 0; p < 256; p++) hb += part[p * Y + j];
    float theta = 1.0f / (float)Y;
    float sc = fmaf(1.0f - theta, rsH[j], hb);
    __shared__ float smin[256], smax[256];
    smin[j] = sc; smax[j] = sc;
    __syncthreads();
    for (int s = blockDim.x >> 1; s > 0; s >>= 1) {
        if (j < s) {
            smin[j] = fminf(smin[j], smin[j + s]);
            smax[j] = fmaxf(smax[j], smax[j + s]);
        }
        __syncthreads();
    }
    float mn = smin[0], mx = smax[0];
    float norm = (sc - mn) / (mx - mn + 1e-8f);
    hm[j] = (norm < 0.5f) ? 0.0f : 1.0f;
}

// ================= launcher (R14/R15 schedule) =================
extern "C" void kernel_launch(void* const* d_in, const int* in_sizes, int n_in,
                              void* d_out, int out_size) {
    const float* x     = (const float*)d_in[0];
    const float* mask0 = (const float*)d_in[1];
    const float* mask1 = (const float*)d_in[2];
    const float* mask2 = (const float*)d_in[3];
    const float* W1 = (const float*)d_in[4];
    const float* b1 = (const float*)d_in[5];
    const float* W2 = (const float*)d_in[6];
    const float* b2 = (const float*)d_in[7];
    const float* W3 = (const float*)d_in[8];
    const float* b3 = (const float*)d_in[9];
    const float* W4 = (const float*)d_in[10];
    const float* b4 = (const float*)d_in[11];
    const float* H1 = (const float*)d_in[12];
    const float* H2 = (const float*)d_in[13];
    const float* H3 = (const float*)d_in[14];
    float* out = (float*)d_out;

    f16 *xh, *xl, *x1h, *x1l, *x2h, *x2l, *x3h, *x3l;
    f16 *B1h, *B2h, *B3h, *B4h;
    float *t1, *t2, *t3, *invn, *sbp, *cbp, *part1, *part2, *part3, *rsH;
    cudaGetSymbolAddress((void**)&xh, g_xh);   cudaGetSymbolAddress((void**)&xl, g_xl);
    cudaGetSymbolAddress((void**)&x1h, g_x1h); cudaGetSymbolAddress((void**)&x1l, g_x1l);
    cudaGetSymbolAddress((void**)&x2h, g_x2h); cudaGetSymbolAddress((void**)&x2l, g_x2l);
    cudaGetSymbolAddress((void**)&x3h, g_x3h); cudaGetSymbolAddress((void**)&x3l, g_x3l);
    cudaGetSymbolAddress((void**)&B1h, g_B1h);
    cudaGetSymbolAddress((void**)&B2h, g_B2h);
    cudaGetSymbolAddress((void**)&B3h, g_B3h);
    cudaGetSymbolAddress((void**)&B4h, g_B4h);
    cudaGetSymbolAddress((void**)&t1, g_t1);
    cudaGetSymbolAddress((void**)&t2, g_t2);
    cudaGetSymbolAddress((void**)&t3, g_t3);
    cudaGetSymbolAddress((void**)&invn, g_invn);
    cudaGetSymbolAddress((void**)&sbp, g_sb);
    cudaGetSymbolAddress((void**)&cbp, g_cb);
    cudaGetSymbolAddress((void**)&part1, g_part1);
    cudaGetSymbolAddress((void**)&part2, g_part2);
    cudaGetSymbolAddress((void**)&part3, g_part3);
    cudaGetSymbolAddress((void**)&rsH, g_rsH);

    float* invn1 = invn;        float* invn2 = invn + 8192;  float* invn3 = invn + 16384;
    float* sb1 = sbp;           float* sb2 = sbp + 8192;     float* sb3 = sbp + 16384;
    float* cb1 = cbp;           float* cb2 = cbp + 8192;     float* cb3 = cbp + 16384;

    static bool inited = false;
    static cudaStream_t s1, s2, s3;
    static cudaEvent_t eFork, eW, eR, eX, eG1, eG2, eG3, eS1, eS2, eS3;
    if (!inited) {
        cudaFuncSetAttribute(gemm_mma<2, 8, 16>,
                             cudaFuncAttributeMaxDynamicSharedMemorySize, SM_28);
        cudaFuncSetAttribute(gemm_mma<1, 8, 4>,
                             cudaFuncAttributeMaxDynamicSharedMemorySize, SM_18);
        cudaFuncSetAttribute(gemm_mma<1, 4, 2>,
                             cudaFuncAttributeMaxDynamicSharedMemorySize, SM_14);
        cudaFuncSetAttribute(gemm_mma<2, 8, 1>,
                             cudaFuncAttributeMaxDynamicSharedMemorySize, SM_28);
        int leastPri, greatestPri;
        cudaDeviceGetStreamPriorityRange(&leastPri, &greatestPri);
        cudaStreamCreateWithPriority(&s1, cudaStreamNonBlocking, leastPri);
        cudaStreamCreateWithPriority(&s2, cudaStreamNonBlocking, leastPri);
        cudaStreamCreateWithPriority(&s3, cudaStreamNonBlocking, leastPri);
        cudaEventCreateWithFlags(&eFork, cudaEventDisableTiming);
        cudaEventCreateWithFlags(&eW, cudaEventDisableTiming);
        cudaEventCreateWithFlags(&eR, cudaEventDisableTiming);
        cudaEventCreateWithFlags(&eX, cudaEventDisableTiming);
        cudaEventCreateWithFlags(&eG1, cudaEventDisableTiming);
        cudaEventCreateWithFlags(&eG2, cudaEventDisableTiming);
        cudaEventCreateWithFlags(&eG3, cudaEventDisableTiming);
        cudaEventCreateWithFlags(&eS1, cudaEventDisableTiming);
        cudaEventCreateWithFlags(&eS2, cudaEventDisableTiming);
        cudaEventCreateWithFlags(&eS3, cudaEventDisableTiming);
        inited = true;
    }

    const int B = 8192;
    const size_t OUT_OFF = (size_t)B * 1000;

    // ---- fork side streams off the capture stream ----
    cudaEventRecord(eFork, 0);
    cudaStreamWaitEvent(s1, eFork, 0);
    cudaStreamWaitEvent(s2, eFork, 0);
    cudaStreamWaitEvent(s3, eFork, 0);

    // s1: weight conversion (gates gemm1)
    split_weights<<<dim3(256, 7), 256, 0, s1>>>(W1, H1, W2, H2, W3, H3, W4,
                                                B1h, B2h, B3h, B4h);
    cudaEventRecord(eW, s1);

    // s2: H rowsums (score gates)
    rowsum_kernel<<<256, 128, 0, s2>>>(H1, 1024, rsH);
    rowsum_kernel<<<128, 128, 0, s2>>>(H2, 256, rsH + 256);
    rowsum_kernel<<<64, 128, 0, s2>>>(H3, 128, rsH + 384);
    cudaEventRecord(eR, s2);

    // s0: x conversion + stats
    rowstats_split<<<B, 256>>>(x, invn1, sb1, xh, xl);
    cudaEventRecord(eX, 0);

    // ======== critical GEMM chain on s0 (combined W+H tiles) ========
    cudaStreamWaitEvent(0, eW, 0);
    gemm_mma<2, 8, 16><<<dim3(4, 64), 256, SM_28>>>(xh, xl, B1h, b1, mask0,
                                                    x1h, x1l, nullptr, t1,
                                                    256, 256);
    cudaEventRecord(eG1, 0);
    gemm_mma<1, 8, 4><<<dim3(2, 128), 256, SM_18>>>(x1h, x1l, B2h, b2, mask1,
                                                    x2h, x2l, nullptr, t2,
                                                    128, 128);
    cudaEventRecord(eG2, 0);
    gemm_mma<1, 4, 2><<<dim3(2, 128), 256, SM_14>>>(x2h, x2l, B3h, b3, mask2,
                                                    x3h, x3l, nullptr, t3,
                                                    64, 64);
    cudaEventRecord(eG3, 0);
    gemm_mma<2, 8, 1><<<dim3(8, 64), 256, SM_28>>>(x3h, x3l, B4h, b4,
                                                   (const float*)nullptr,
                                                   (f16*)nullptr, (f16*)nullptr,
                                                   out, (float*)nullptr,
                                                   1000, 0);

    // ======== layer-1 hebbian on s1 ========
    cudaStreamWaitEvent(s1, eG1, 0);
    cudaStreamWaitEvent(s1, eX, 0);
    cudaStreamWaitEvent(s1, eR, 0);
    cb_kernel<<<1024, 256, 0, s1>>>(t1, 256, invn1, sb1, cb1);
    hebb_kernel<<<256, 256, 0, s1>>>(t1, 256, cb1, part1);
    score_kernel<<<1, 256, 0, s1>>>(rsH, part1, 256, out + OUT_OFF);
    cudaEventRecord(eS1, s1);

    // ======== layer-2 hebbian on s2 ========
    cudaStreamWaitEvent(s2, eG1, 0);
    rowstats_hl<<<B, 128, 0, s2>>>(x1h, x1l, 256, invn2, sb2);
    cudaStreamWaitEvent(s2, eG2, 0);
    cb_kernel<<<1024, 256, 0, s2>>>(t2, 128, invn2, sb2, cb2);
    hebb_kernel<<<256, 128, 0, s2>>>(t2, 128, cb2, part2);
    score_kernel<<<1, 128, 0, s2>>>(rsH + 256, part2, 128, out + OUT_OFF + 256);
    cudaEventRecord(eS2, s2);

    // ======== layer-3 hebbian on s3 ========
    cudaStreamWaitEvent(s3, eG2, 0);
    rowstats_hl<<<B, 128, 0, s3>>>(x2h, x2l, 128, invn3, sb3);
    cudaStreamWaitEvent(s3, eG3, 0);
    cudaStreamWaitEvent(s3, eR, 0);
    cb_kernel<<<1024, 256, 0, s3>>>(t3, 64, invn3, sb3, cb3);
    hebb_kernel<<<256, 64, 0, s3>>>(t3, 64, cb3, part3);
    score_kernel<<<1, 64, 0, s3>>>(rsH + 384, part3, 64, out + OUT_OFF + 384);
    cudaEventRecord(eS3, s3);

    // ---- join ----
    cudaStreamWaitEvent(0, eS1, 0);
    cudaStreamWaitEvent(0, eS2, 0);
    cudaStreamWaitEvent(0, eS3, 0);
}

// round 17
// speedup vs baseline: 1.2493x; 1.1036x over previous
#include <cuda_runtime.h>
#include <cuda_fp16.h>
#include <cstdint>
#include <cstddef>

using f16 = __half;

// ================= device scratch (no allocations allowed) =================
__device__ __align__(16) f16 g_xh [8192 * 1024];
__device__ __align__(16) f16 g_xl [8192 * 1024];
__device__ __align__(16) f16 g_x1h[8192 * 256];
__device__ __align__(16) f16 g_x1l[8192 * 256];
__device__ __align__(16) f16 g_x2h[8192 * 128];
__device__ __align__(16) f16 g_x2l[8192 * 128];
__device__ __align__(16) f16 g_x3h[8192 * 64];
__device__ __align__(16) f16 g_x3l[8192 * 64];
__device__ __align__(16) f16 g_B1h[512 * 1024];
__device__ __align__(16) f16 g_B2h[256 * 256];
__device__ __align__(16) f16 g_B3h[128 * 128];
__device__ __align__(16) f16 g_B4h[1024 * 64];
__device__ float g_t1[8192 * 256];
__device__ float g_t2[8192 * 128];
__device__ float g_t3[8192 * 64];
__device__ float g_invn[3][8192];
__device__ float g_sb[3][8192];
__device__ float g_cb[3][8192];
__device__ float g_part1[256 * 256];
__device__ float g_part2[256 * 128];
__device__ float g_part3[256 * 64];
__device__ float g_rsH[512];          // slots: 0 / 256 / 384

// ================= helpers =================
__device__ __forceinline__ uint32_t smem_u32(const void* p) {
    uint32_t a;
    asm("{ .reg .u64 t; cvta.to.shared.u64 t, %1; cvt.u32.u64 %0, t; }"
        : "=r"(a) : "l"(p));
    return a;
}
__device__ __forceinline__ void ldsm4(uint32_t* r, uint32_t addr) {
    asm volatile("ldmatrix.sync.aligned.m8n8.x4.shared.b16 {%0,%1,%2,%3}, [%4];"
                 : "=r"(r[0]), "=r"(r[1]), "=r"(r[2]), "=r"(r[3]) : "r"(addr));
}
__device__ __forceinline__ void mma16816(float* d, const uint32_t* a, const uint32_t* b) {
    asm volatile(
        "mma.sync.aligned.m16n8k16.row.col.f32.f16.f16.f32 "
        "{%0,%1,%2,%3}, {%4,%5,%6,%7}, {%8,%9}, {%0,%1,%2,%3};"
        : "+f"(d[0]), "+f"(d[1]), "+f"(d[2]), "+f"(d[3])
        : "r"(a[0]), "r"(a[1]), "r"(a[2]), "r"(a[3]), "r"(b[0]), "r"(b[1]));
}
__device__ __forceinline__ void cp16(uint32_t dst, const void* src) {
    asm volatile("cp.async.cg.shared.global [%0], [%1], 16;"
                 :: "r"(dst), "l"(src) : "memory");
}
__device__ __forceinline__ void split1(float v, f16& h, f16& l) {
    h = __float2half_rn(v);
    l = __float2half_rn(v - __half2float(h));
}
__device__ __forceinline__ float warp_sum(float v) {
#pragma unroll
    for (int o = 16; o; o >>= 1) v += __shfl_down_sync(0xffffffffu, v, o);
    return v;
}

// ================= fp16 GEMM, KC=64 chunks, 2-stage, unrolled NC ===========
// TWO=true : D = (Ah+Al).Bh  (2-pass)  | TWO=false : D = Ah.Bh (1-pass, Al unused)
#define LDH3 72                          // halfwords per row (64 + 8 pad)

template <int MB, int NB, int NCc, bool TWO>
__global__ __launch_bounds__(256, 2)
void gemm_mma(const f16* __restrict__ Ah, const f16* __restrict__ Al,
              const f16* __restrict__ Bh,
              const float* __restrict__ bias, const float* __restrict__ mask,
              f16* __restrict__ Xh, f16* __restrict__ Xl,
              float* __restrict__ Xf, float* __restrict__ Tout,
              int NW, int NT) {
    constexpr int K = 64 * NCc;
    constexpr int BM = 64 * MB;
    constexpr int BN = 16 * NB;
    constexpr int TILE_A = BM * LDH3 * 2;      // one A buffer
    constexpr int TILE_Bb = BN * LDH3 * 2;
    constexpr int NA = TWO ? 2 : 1;            // staged A buffers
    constexpr int STG = NA * TILE_A + TILE_Bb;
    extern __shared__ char smem[];
    const uint32_t sbase = smem_u32(smem);
    const int tid = threadIdx.x;
    const int lane = tid & 31;
    const int warp = tid >> 5;
    const int wm = warp >> 1;                  // 0..3
    const int wn = warp & 1;                   // 0..1
    const int bm = blockIdx.y * BM;
    const int bn = blockIdx.x * BN;

    const int row32 = tid >> 3;                // 0..31
    const int c8 = (tid & 7) * 8;              // halfword offset 0..56

    float acc[MB][NB][4];
#pragma unroll
    for (int i = 0; i < MB; i++)
#pragma unroll
        for (int j = 0; j < NB; j++)
#pragma unroll
            for (int q = 0; q < 4; q++) acc[i][j][q] = 0.f;

    auto issue = [&](int c, int buf) {
        int k0 = c << 6;
        uint32_t st = sbase + buf * STG;
#pragma unroll
        for (int i = 0; i < 2 * MB; i++) {     // A: BM rows, 32 per round
            int r = row32 + 32 * i;
            uint32_t off = (uint32_t)(r * LDH3 + c8) * 2;
            const size_t ao = (size_t)(bm + r) * K + k0 + c8;
            cp16(st + off, Ah + ao);
            if constexpr (TWO) cp16(st + TILE_A + off, Al + ao);
        }
#pragma unroll
        for (int i = 0; i < NB / 2; i++) {     // B: BN rows, 32 per round
            int r = row32 + 32 * i;
            uint32_t off = (uint32_t)(r * LDH3 + c8) * 2;
            const size_t bo = (size_t)(bn + r) * K + k0 + c8;
            cp16(st + NA * TILE_A + off, Bh + bo);
        }
    };

    // prologue: fill up to 2 stages
#pragma unroll
    for (int s = 0; s < 2; s++) {
        if (s < NCc) issue(s, s);
        asm volatile("cp.async.commit_group;" ::: "memory");
    }

    const int rl = lane & 15, ka = (lane >> 4) * 8;
    const int sec = lane >> 3;
    const int nloc = ((sec & 2) ? 8 : 0) + (lane & 7);
    const int kb = (sec & 1) * 8;

#pragma unroll
    for (int c = 0; c < NCc; c++) {
        asm volatile("cp.async.wait_group 1;" ::: "memory");
        __syncthreads();
        const uint32_t stb = sbase + (uint32_t)(c & 1) * STG;
#pragma unroll
        for (int kk = 0; kk < 64; kk += 16) {
            uint32_t ah[MB][4], al[MB][4];
#pragma unroll
            for (int i = 0; i < MB; i++) {
                uint32_t off =
                    (uint32_t)((wm * (MB * 16) + i * 16 + rl) * LDH3 + kk + ka) * 2;
                ldsm4(ah[i], stb + off);
                if constexpr (TWO) ldsm4(al[i], stb + TILE_A + off);
            }
            uint32_t b[NB][2];
#pragma unroll
            for (int p = 0; p < NB / 2; p++) {
                uint32_t r4[4];
                ldsm4(r4, stb + NA * TILE_A +
                          (uint32_t)((wn * (NB * 8) + p * 16 + nloc) * LDH3 + kk + kb) * 2);
                b[2 * p][0] = r4[0]; b[2 * p][1] = r4[1];
                b[2 * p + 1][0] = r4[2]; b[2 * p + 1][1] = r4[3];
            }
#pragma unroll
            for (int i = 0; i < MB; i++)
#pragma unroll
                for (int j = 0; j < NB; j++) {
                    mma16816(acc[i][j], ah[i], b[j]);
                    if constexpr (TWO) mma16816(acc[i][j], al[i], b[j]);
                }
        }
        __syncthreads();
        if (c + 2 < NCc) issue(c + 2, (c + 2) & 1);
        asm volatile("cp.async.commit_group;" ::: "memory");
    }

    // ---- epilogue ----
    const int rq = lane >> 2;
    const int cq = (lane & 3) * 2;
    const int Ntot = NW + NT;
#pragma unroll
    for (int i = 0; i < MB; i++) {
        int r0 = bm + wm * (MB * 16) + i * 16 + rq;
        int r1 = r0 + 8;
#pragma unroll
        for (int j = 0; j < NB; j++) {
            int c0 = bn + wn * (NB * 8) + j * 8 + cq;
            float v00 = acc[i][j][0], v01 = acc[i][j][1];
            float v10 = acc[i][j][2], v11 = acc[i][j][3];
            if (c0 < NW) {
                float bb0 = bias[c0], bb1 = bias[c0 + 1];
                v00 = fmaxf(v00 + bb0, 0.f); v01 = fmaxf(v01 + bb1, 0.f);
                v10 = fmaxf(v10 + bb0, 0.f); v11 = fmaxf(v11 + bb1, 0.f);
                if (mask) {
                    float m0 = mask[c0], m1 = mask[c0 + 1];
                    v00 *= m0; v01 *= m1; v10 *= m0; v11 *= m1;
                }
                if (Xh) {
                    f16 h, l;
                    __half2 hp, lp;
                    split1(v00, h, l); hp.x = h; lp.x = l;
                    split1(v01, h, l); hp.y = h; lp.y = l;
                    *reinterpret_cast<__half2*>(Xh + (size_t)r0 * NW + c0) = hp;
                    *reinterpret_cast<__half2*>(Xl + (size_t)r0 * NW + c0) = lp;
                    split1(v10, h, l); hp.x = h; lp.x = l;
                    split1(v11, h, l); hp.y = h; lp.y = l;
                    *reinterpret_cast<__half2*>(Xh + (size_t)r1 * NW + c0) = hp;
                    *reinterpret_cast<__half2*>(Xl + (size_t)r1 * NW + c0) = lp;
                } else {
                    *reinterpret_cast<float2*>(Xf + (size_t)r0 * NW + c0) =
                        make_float2(v00, v01);
                    *reinterpret_cast<float2*>(Xf + (size_t)r1 * NW + c0) =
                        make_float2(v10, v11);
                }
            } else if (c0 < Ntot) {
                int tc = c0 - NW;
                *reinterpret_cast<float2*>(Tout + (size_t)r0 * NT + tc) =
                    make_float2(v00, v01);
                *reinterpret_cast<float2*>(Tout + (size_t)r1 * NT + tc) =
                    make_float2(v10, v11);
            }
        }
    }
}

// smem sizes (2 stages, KC=64)
#define SM_28   (2 * (2 * (128 * LDH3 * 2) + 128 * LDH3 * 2))  // 110592 (2-pass 128x128)
#define SM_28_1 (2 * (1 * (128 * LDH3 * 2) + 128 * LDH3 * 2))  // 73728  (1-pass 128x128)
#define SM_18   (2 * (2 * (64 * LDH3 * 2) + 128 * LDH3 * 2))   // 73728
#define SM_14   (2 * (2 * (64 * LDH3 * 2) + 64 * LDH3 * 2))    // 55296

// ================= conversion kernels =================
__global__ void split_weights(const float* W1, const float* H1, const float* W2,
                              const float* H2, const float* W3, const float* H3,
                              const float* W4,
                              f16* B1h, f16* B2h, f16* B3h, f16* B4h) {
    const float* src; f16* dh; int n, ntot;
    switch (blockIdx.y) {
        case 0: src = W1; dh = B1h;            n = 256*1024; ntot = n; break;
        case 1: src = H1; dh = B1h + 256*1024; n = 256*1024; ntot = n; break;
        case 2: src = W2; dh = B2h;            n = 128*256;  ntot = n; break;
        case 3: src = H2; dh = B2h + 128*256;  n = 128*256;  ntot = n; break;
        case 4: src = W3; dh = B3h;            n = 64*128;   ntot = n; break;
        case 5: src = H3; dh = B3h + 64*128;   n = 64*128;   ntot = n; break;
        default: src = W4; dh = B4h;           n = 1000*64;  ntot = 1024*64; break;
    }
    for (int i = (blockIdx.x * blockDim.x + threadIdx.x) * 4; i < ntot;
         i += gridDim.x * blockDim.x * 4) {
        float4 v;
        if (i + 3 < n) v = *reinterpret_cast<const float4*>(src + i);
        else v = make_float4(i < n ? src[i] : 0.f, i + 1 < n ? src[i + 1] : 0.f,
                             i + 2 < n ? src[i + 2] : 0.f, i + 3 < n ? src[i + 3] : 0.f);
        __half2 hp0, hp1;
        hp0.x = __float2half_rn(v.x); hp0.y = __float2half_rn(v.y);
        hp1.x = __float2half_rn(v.z); hp1.y = __float2half_rn(v.w);
        reinterpret_cast<__half2*>(dh + i)[0] = hp0;
        reinterpret_cast<__half2*>(dh + i)[1] = hp1;
    }
}

__global__ void rowstats_split(const float* __restrict__ X, float* __restrict__ invn,
                               float* __restrict__ rs, f16* __restrict__ xh,
                               f16* __restrict__ xl) {
    int b = blockIdx.x, t = threadIdx.x;   // 256 threads
    const float* row = X + (size_t)b * 1024;
    float4 v = *reinterpret_cast<const float4*>(row + t * 4);
    f16 h, l;
    __half2 hp0, hp1, lp0, lp1;
    split1(v.x, h, l); hp0.x = h; lp0.x = l;
    split1(v.y, h, l); hp0.y = h; lp0.y = l;
    split1(v.z, h, l); hp1.x = h; lp1.x = l;
    split1(v.w, h, l); hp1.y = h; lp1.y = l;
    size_t o = (size_t)b * 1024 + t * 4;
    reinterpret_cast<__half2*>(xh + o)[0] = hp0;
    reinterpret_cast<__half2*>(xh + o)[1] = hp1;
    reinterpret_cast<__half2*>(xl + o)[0] = lp0;
    reinterpret_cast<__half2*>(xl + o)[1] = lp1;
    float s = v.x + v.y + v.z + v.w;
    float ss = fmaf(v.x, v.x, fmaf(v.y, v.y, fmaf(v.z, v.z, v.w * v.w)));
    __shared__ float shs[8], shss[8];
    s = warp_sum(s); ss = warp_sum(ss);
    int w = t >> 5, lid = t & 31;
    if (lid == 0) { shs[w] = s; shss[w] = ss; }
    __syncthreads();
    if (t == 0) {
        float ts = 0.f, tss = 0.f;
#pragma unroll
        for (int i = 0; i < 8; i++) { ts += shs[i]; tss += shss[i]; }
        invn[b] = rsqrtf(tss);
        rs[b] = ts;
    }
}

__global__ void rowstats_hl(const f16* __restrict__ hi, const f16* __restrict__ lo,
                            int D, float* __restrict__ invn, float* __restrict__ rs) {
    int b = blockIdx.x, t = threadIdx.x;   // 128 threads
    float s = 0.f, ss = 0.f;
    for (int i = t; i < D; i += 128) {
        float v = __half2float(hi[(size_t)b * D + i]) +
                  __half2float(lo[(size_t)b * D + i]);
        s += v;
        ss = fmaf(v, v, ss);
    }
    __shared__ float shs[4], shss[4];
    s = warp_sum(s); ss = warp_sum(ss);
    int w = t >> 5, lid = t & 31;
    if (lid == 0) { shs[w] = s; shss[w] = ss; }
    __syncthreads();
    if (t == 0) {
        float ts = 0.f, tss = 0.f;
#pragma unroll
        for (int i = 0; i < 4; i++) { ts += shs[i]; tss += shss[i]; }
        invn[b] = rsqrtf(tss);
        rs[b] = ts;
    }
}

// ================= hebbian-path kernels =================
__global__ void cb_kernel(const float* __restrict__ T, int Y,
                          const float* __restrict__ invnx, const float* __restrict__ sb,
                          float* __restrict__ cb) {
    int wrp = (blockIdx.x * blockDim.x + threadIdx.x) >> 5;
    int lane = threadIdx.x & 31;
    if (wrp >= 8192) return;
    const float* row = T + (size_t)wrp * Y;
    float ss = 0.f;
    for (int i = lane; i < Y; i += 32) { float v = row[i]; ss = fmaf(v, v, ss); }
    ss = warp_sum(ss);
    if (lane == 0) cb[wrp] = sb[wrp] * invnx[wrp] * rsqrtf(ss);
}

__global__ void hebb_kernel(const float* __restrict__ T, int Y,
                            const float* __restrict__ cb, float* __restrict__ part) {
    int j = threadIdx.x;
    int b0 = blockIdx.x * 32;
    float a0 = 0.f, a1 = 0.f, a2 = 0.f, a3 = 0.f;
#pragma unroll
    for (int b = b0; b < b0 + 32; b += 4) {
        a0 = fmaf(T[(size_t)b * Y + j],       cb[b],     a0);
        a1 = fmaf(T[(size_t)(b + 1) * Y + j], cb[b + 1], a1);
        a2 = fmaf(T[(size_t)(b + 2) * Y + j], cb[b + 2], a2);
        a3 = fmaf(T[(size_t)(b + 3) * Y + j], cb[b + 3], a3);
    }
    part[blockIdx.x * Y + j] = (a0 + a1) + (a2 + a3);
}

__global__ void rowsum_kernel(const float* __restrict__ H, int D,
                              float* __restrict__ out) {
    int row = blockIdx.x, t = threadIdx.x;   // 128 threads
    float s = 0.f;
    for (int i = t; i < D; i += 128) s += H[(size_t)row * D + i];
    __shared__ float sh[4];
    s = warp_sum(s);
    if ((t & 31) == 0) sh[t >> 5] = s;
    __syncthreads();
    if (t == 0) out[row] = sh[0] + sh[1] + sh[2] + sh[3];
}

__global__ void score_kernel(const float* __restrict__ rsH, const float* __restrict__ part,
                             int Y, float* __restrict__ hm) {
    int j = threadIdx.x;
    float hb = 0.f;
    for (int p = 0; p < 256; p++) hb += part[p * Y + j];
    float theta = 1.0f / (float)Y;
    float sc = fmaf(1.0f - theta, rsH[j], hb);
    __shared__ float smin[256], smax[256];
    smin[j] = sc; smax[j] = sc;
    __syncthreads();
    for (int s = blockDim.x >> 1; s > 0; s >>= 1) {
        if (j < s) {
            smin[j] = fminf(smin[j], smin[j + s]);
            smax[j] = fmaxf(smax[j], smax[j + s]);
        }
        __syncthreads();
    }
    float mn = smin[0], mx = smax[0];
    float norm = (sc - mn) / (mx - mn + 1e-8f);
    hm[j] = (norm < 0.5f) ? 0.0f : 1.0f;
}

// ================= launcher =================
extern "C" void kernel_launch(void* const* d_in, const int* in_sizes, int n_in,
                              void* d_out, int out_size) {
    const float* x     = (const float*)d_in[0];
    const float* mask0 = (const float*)d_in[1];
    const float* mask1 = (const float*)d_in[2];
    const float* mask2 = (const float*)d_in[3];
    const float* W1 = (const float*)d_in[4];
    const float* b1 = (const float*)d_in[5];
    const float* W2 = (const float*)d_in[6];
    const float* b2 = (const float*)d_in[7];
    const float* W3 = (const float*)d_in[8];
    const float* b3 = (const float*)d_in[9];
    const float* W4 = (const float*)d_in[10];
    const float* b4 = (const float*)d_in[11];
    const float* H1 = (const float*)d_in[12];
    const float* H2 = (const float*)d_in[13];
    const float* H3 = (const float*)d_in[14];
    float* out = (float*)d_out;

    f16 *xh, *xl, *x1h, *x1l, *x2h, *x2l, *x3h, *x3l;
    f16 *B1h, *B2h, *B3h, *B4h;
    float *t1, *t2, *t3, *invn, *sbp, *cbp, *part1, *part2, *part3, *rsH;
    cudaGetSymbolAddress((void**)&xh, g_xh);   cudaGetSymbolAddress((void**)&xl, g_xl);
    cudaGetSymbolAddress((void**)&x1h, g_x1h); cudaGetSymbolAddress((void**)&x1l, g_x1l);
    cudaGetSymbolAddress((void**)&x2h, g_x2h); cudaGetSymbolAddress((void**)&x2l, g_x2l);
    cudaGetSymbolAddress((void**)&x3h, g_x3h); cudaGetSymbolAddress((void**)&x3l, g_x3l);
    cudaGetSymbolAddress((void**)&B1h, g_B1h);
    cudaGetSymbolAddress((void**)&B2h, g_B2h);
    cudaGetSymbolAddress((void**)&B3h, g_B3h);
    cudaGetSymbolAddress((void**)&B4h, g_B4h);
    cudaGetSymbolAddress((void**)&t1, g_t1);
    cudaGetSymbolAddress((void**)&t2, g_t2);
    cudaGetSymbolAddress((void**)&t3, g_t3);
    cudaGetSymbolAddress((void**)&invn, g_invn);
    cudaGetSymbolAddress((void**)&sbp, g_sb);
    cudaGetSymbolAddress((void**)&cbp, g_cb);
    cudaGetSymbolAddress((void**)&part1, g_part1);
    cudaGetSymbolAddress((void**)&part2, g_part2);
    cudaGetSymbolAddress((void**)&part3, g_part3);
    cudaGetSymbolAddress((void**)&rsH, g_rsH);

    float* invn1 = invn;        float* invn2 = invn + 8192;  float* invn3 = invn + 16384;
    float* sb1 = sbp;           float* sb2 = sbp + 8192;     float* sb3 = sbp + 16384;
    float* cb1 = cbp;           float* cb2 = cbp + 8192;     float* cb3 = cbp + 16384;

    static bool inited = false;
    static cudaStream_t s1, s2, s3;
    static cudaEvent_t eFork, eW, eR, eX, eG1, eG2, eG3, eS1, eS2, eS3;
    if (!inited) {
        cudaFuncSetAttribute(gemm_mma<2, 8, 16, true>,
                             cudaFuncAttributeMaxDynamicSharedMemorySize, SM_28);
        cudaFuncSetAttribute(gemm_mma<2, 8, 16, false>,
                             cudaFuncAttributeMaxDynamicSharedMemorySize, SM_28_1);
        cudaFuncSetAttribute(gemm_mma<1, 8, 4, true>,
                             cudaFuncAttributeMaxDynamicSharedMemorySize, SM_18);
        cudaFuncSetAttribute(gemm_mma<1, 4, 2, true>,
                             cudaFuncAttributeMaxDynamicSharedMemorySize, SM_14);
        cudaFuncSetAttribute(gemm_mma<2, 8, 1, true>,
                             cudaFuncAttributeMaxDynamicSharedMemorySize, SM_28);
        int leastPri, greatestPri;
        cudaDeviceGetStreamPriorityRange(&leastPri, &greatestPri);
        cudaStreamCreateWithPriority(&s1, cudaStreamNonBlocking, leastPri);
        cudaStreamCreateWithPriority(&s2, cudaStreamNonBlocking, leastPri);
        cudaStreamCreateWithPriority(&s3, cudaStreamNonBlocking, leastPri);
        cudaEventCreateWithFlags(&eFork, cudaEventDisableTiming);
        cudaEventCreateWithFlags(&eW, cudaEventDisableTiming);
        cudaEventCreateWithFlags(&eR, cudaEventDisableTiming);
        cudaEventCreateWithFlags(&eX, cudaEventDisableTiming);
        cudaEventCreateWithFlags(&eG1, cudaEventDisableTiming);
        cudaEventCreateWithFlags(&eG2, cudaEventDisableTiming);
        cudaEventCreateWithFlags(&eG3, cudaEventDisableTiming);
        cudaEventCreateWithFlags(&eS1, cudaEventDisableTiming);
        cudaEventCreateWithFlags(&eS2, cudaEventDisableTiming);
        cudaEventCreateWithFlags(&eS3, cudaEventDisableTiming);
        inited = true;
    }

    const int B = 8192;
    const size_t OUT_OFF = (size_t)B * 1000;

    // ---- fork side streams off the capture stream ----
    cudaEventRecord(eFork, 0);
    cudaStreamWaitEvent(s1, eFork, 0);
    cudaStreamWaitEvent(s2, eFork, 0);
    cudaStreamWaitEvent(s3, eFork, 0);

    // s1: weight conversion (gates g1W and g1T)
    split_weights<<<dim3(256, 7), 256, 0, s1>>>(W1, H1, W2, H2, W3, H3, W4,
                                                B1h, B2h, B3h, B4h);
    cudaEventRecord(eW, s1);

    // s2: H rowsums (score gates)
    rowsum_kernel<<<256, 128, 0, s2>>>(H1, 1024, rsH);
    rowsum_kernel<<<128, 128, 0, s2>>>(H2, 256, rsH + 256);
    rowsum_kernel<<<64, 128, 0, s2>>>(H3, 128, rsH + 384);
    cudaEventRecord(eR, s2);

    // s0: x conversion + stats
    rowstats_split<<<B, 256>>>(x, invn1, sb1, xh, xl);
    cudaEventRecord(eX, 0);

    // ======== g1T (hebbian columns, 1-pass) on s1 — co-runs with g1W =======
    cudaStreamWaitEvent(s1, eX, 0);
    gemm_mma<2, 8, 16, false><<<dim3(2, 64), 256, SM_28_1, s1>>>(
        xh, xh, B1h + 256 * 1024, (const float*)nullptr, (const float*)nullptr,
        (f16*)nullptr, (f16*)nullptr, (float*)nullptr, t1, 0, 256);

    // ======== critical W chain on s0 ========
    cudaStreamWaitEvent(0, eW, 0);
    gemm_mma<2, 8, 16, true><<<dim3(2, 64), 256, SM_28>>>(xh, xl, B1h, b1, mask0,
                                                          x1h, x1l, nullptr,
                                                          nullptr, 256, 0);
    cudaEventRecord(eG1, 0);
    gemm_mma<1, 8, 4, true><<<dim3(2, 128), 256, SM_18>>>(x1h, x1l, B2h, b2, mask1,
                                                          x2h, x2l, nullptr, t2,
                                                          128, 128);
    cudaEventRecord(eG2, 0);
    gemm_mma<1, 4, 2, true><<<dim3(2, 128), 256, SM_14>>>(x2h, x2l, B3h, b3, mask2,
                                                          x3h, x3l, nullptr, t3,
                                                          64, 64);
    cudaEventRecord(eG3, 0);
    gemm_mma<2, 8, 1, true><<<dim3(8, 64), 256, SM_28>>>(x3h, x3l, B4h, b4,
                                                         (const float*)nullptr,
                                                         (f16*)nullptr, (f16*)nullptr,
                                                         out, (float*)nullptr,
                                                         1000, 0);

    // ======== layer-1 hebbian on s1 (after g1T, program order) ========
    cudaStreamWaitEvent(s1, eR, 0);
    cb_kernel<<<1024, 256, 0, s1>>>(t1, 256, invn1, sb1, cb1);
    hebb_kernel<<<256, 256, 0, s1>>>(t1, 256, cb1, part1);
    score_kernel<<<1, 256, 0, s1>>>(rsH, part1, 256, out + OUT_OFF);
    cudaEventRecord(eS1, s1);

    // ======== layer-2 hebbian on s2 ========
    cudaStreamWaitEvent(s2, eG1, 0);
    rowstats_hl<<<B, 128, 0, s2>>>(x1h, x1l, 256, invn2, sb2);
    cudaStreamWaitEvent(s2, eG2, 0);
    cb_kernel<<<1024, 256, 0, s2>>>(t2, 128, invn2, sb2, cb2);
    hebb_kernel<<<256, 128, 0, s2>>>(t2, 128, cb2, part2);
    score_kernel<<<1, 128, 0, s2>>>(rsH + 256, part2, 128, out + OUT_OFF + 256);
    cudaEventRecord(eS2, s2);

    // ======== layer-3 hebbian on s3 ========
    cudaStreamWaitEvent(s3, eG2, 0);
    rowstats_hl<<<B, 128, 0, s3>>>(x2h, x2l, 128, invn3, sb3);
    cudaStreamWaitEvent(s3, eG3, 0);
    cudaStreamWaitEvent(s3, eR, 0);
    cb_kernel<<<1024, 256, 0, s3>>>(t3, 64, invn3, sb3, cb3);
    hebb_kernel<<<256, 64, 0, s3>>>(t3, 64, cb3, part3);
    score_kernel<<<1, 64, 0, s3>>>(rsH + 384, part3, 64, out + OUT_OFF + 384);
    cudaEventRecord(eS3, s3);

    // ---- join ----
    cudaStreamWaitEvent(0, eS1, 0);
    cudaStreamWaitEvent(0, eS2, 0);
    cudaStreamWaitEvent(0, eS3, 0);
}